// round 1
// baseline (speedup 1.0000x reference)
#include <cuda_runtime.h>

#define TOK   4096
#define EMB   512
#define QKVN  1536
#define HEADS 8
#define DH    64
#define SCALE 0.125f

// strides
#define HSTRIDE (TOK * DH)           // 262144
#define PSTRIDE (HEADS * TOK * DH)   // 2097152

// scratch (device globals are the sanctioned scratch mechanism)
__device__ float g_qkv[3 * HEADS * TOK * DH];        // [part][h][n][d], ~25 MB
__device__ float g_qsum[HEADS * DH];                 // [h][d]
__device__ float g_ktv[HEADS * DH * DH];             // [h][d1][d2]
__device__ float g_ktv_part[16 * HEADS * DH * DH];   // [split][h][d1][d2]

// ---------------------------------------------------------------------------
// Kernel 1: qkv[n][o] = sum_e x[e][n] * W[e][o] + b[o], scattered to g_qkv
// M=4096 (n), N=1536 (o), K=512 (e). Both operands K-major in gmem.
// ---------------------------------------------------------------------------
#define BM 128
#define BN 128
#define BK 16

__global__ __launch_bounds__(256) void qkv_gemm(const float* __restrict__ x,
                                                const float* __restrict__ W,
                                                const float* __restrict__ bias) {
    __shared__ float As[BK][BM];
    __shared__ float Bs[BK][BN];

    const int tid = threadIdx.x;
    const int n0 = blockIdx.y * BM;
    const int o0 = blockIdx.x * BN;
    const int ty = tid >> 4;          // 0..15 -> row group
    const int tx = tid & 15;          // 0..15 -> col group

    float acc[8][8];
#pragma unroll
    for (int i = 0; i < 8; i++)
#pragma unroll
        for (int j = 0; j < 8; j++) acc[i][j] = 0.f;

    for (int kt = 0; kt < EMB; kt += BK) {
        // cooperative load: 16x128 floats each = 512 float4s, 2 per thread
#pragma unroll
        for (int i = 0; i < 2; i++) {
            int lin = tid + i * 256;
            int k   = lin >> 5;
            int m4  = (lin & 31) << 2;
            float4 va = *reinterpret_cast<const float4*>(&x[(size_t)(kt + k) * TOK + n0 + m4]);
            As[k][m4 + 0] = va.x; As[k][m4 + 1] = va.y;
            As[k][m4 + 2] = va.z; As[k][m4 + 3] = va.w;
            float4 vb = *reinterpret_cast<const float4*>(&W[(size_t)(kt + k) * QKVN + o0 + m4]);
            Bs[k][m4 + 0] = vb.x; Bs[k][m4 + 1] = vb.y;
            Bs[k][m4 + 2] = vb.z; Bs[k][m4 + 3] = vb.w;
        }
        __syncthreads();

#pragma unroll
        for (int k = 0; k < BK; k++) {
            float ra[8], rb[8];
            float4 a0 = *reinterpret_cast<const float4*>(&As[k][ty * 8]);
            float4 a1 = *reinterpret_cast<const float4*>(&As[k][ty * 8 + 4]);
            ra[0] = a0.x; ra[1] = a0.y; ra[2] = a0.z; ra[3] = a0.w;
            ra[4] = a1.x; ra[5] = a1.y; ra[6] = a1.z; ra[7] = a1.w;
            float4 b0 = *reinterpret_cast<const float4*>(&Bs[k][tx * 8]);
            float4 b1 = *reinterpret_cast<const float4*>(&Bs[k][tx * 8 + 4]);
            rb[0] = b0.x; rb[1] = b0.y; rb[2] = b0.z; rb[3] = b0.w;
            rb[4] = b1.x; rb[5] = b1.y; rb[6] = b1.z; rb[7] = b1.w;
#pragma unroll
            for (int i = 0; i < 8; i++)
#pragma unroll
                for (int j = 0; j < 8; j++) acc[i][j] += ra[i] * rb[j];
        }
        __syncthreads();
    }

    // epilogue: add bias, scatter to [part][h][n][d]
    float bv[8];
#pragma unroll
    for (int j = 0; j < 8; j++) bv[j] = bias[o0 + tx * 8 + j];

#pragma unroll
    for (int i = 0; i < 8; i++) {
        int n = n0 + ty * 8 + i;
#pragma unroll
        for (int j4 = 0; j4 < 2; j4++) {
            int o    = o0 + tx * 8 + j4 * 4;
            int part = o >> 9;
            int r    = o & 511;
            int h    = r >> 6;
            int d    = r & 63;
            float4 v;
            v.x = acc[i][j4 * 4 + 0] + bv[j4 * 4 + 0];
            v.y = acc[i][j4 * 4 + 1] + bv[j4 * 4 + 1];
            v.z = acc[i][j4 * 4 + 2] + bv[j4 * 4 + 2];
            v.w = acc[i][j4 * 4 + 3] + bv[j4 * 4 + 3];
            *reinterpret_cast<float4*>(
                &g_qkv[(size_t)part * PSTRIDE + (size_t)h * HSTRIDE + (size_t)n * DH + d]) = v;
        }
    }
}

// ---------------------------------------------------------------------------
// Kernel 2: qsum[h][d] = sum_n Q[h][n][d]   (deterministic, one block/head)
// ---------------------------------------------------------------------------
__global__ __launch_bounds__(256) void qsum_kernel() {
    int h = blockIdx.x;
    int tid = threadIdx.x;
    int d = tid & 63;
    int s = tid >> 6;   // 0..3
    const float* Q = &g_qkv[(size_t)h * HSTRIDE];
    float sum = 0.f;
    for (int n = s; n < TOK; n += 4) sum += Q[(size_t)n * DH + d];
    __shared__ float red[4][64];
    red[s][d] = sum;
    __syncthreads();
    if (tid < 64)
        g_qsum[h * 64 + tid] = red[0][tid] + red[1][tid] + red[2][tid] + red[3][tid];
}

// ---------------------------------------------------------------------------
// Kernel 3: partial KtV[h][d1][d2] = sum_{n in split} K[h][n][d1]*V[h][n][d2]
// grid (8 heads, 16 splits). No atomics -> deterministic.
// ---------------------------------------------------------------------------
__global__ __launch_bounds__(256) void ktv_kernel() {
    int h = blockIdx.x;
    int split = blockIdx.y;
    const float* Kp = &g_qkv[(size_t)1 * PSTRIDE + (size_t)h * HSTRIDE];
    const float* Vp = &g_qkv[(size_t)2 * PSTRIDE + (size_t)h * HSTRIDE];

    __shared__ float sK[32][64];
    __shared__ float sV[32][64];

    int tid = threadIdx.x;
    int d1b = (tid >> 4) << 2;
    int d2b = (tid & 15) << 2;
    float acc[4][4];
#pragma unroll
    for (int i = 0; i < 4; i++)
#pragma unroll
        for (int j = 0; j < 4; j++) acc[i][j] = 0.f;

    int nbase = split * 256;
    for (int nc = 0; nc < 256; nc += 32) {
#pragma unroll
        for (int i = 0; i < 2; i++) {
            int lin = tid + i * 256;
            int r = lin >> 4;
            int c = (lin & 15) << 2;
            *reinterpret_cast<float4*>(&sK[r][c]) =
                *reinterpret_cast<const float4*>(&Kp[(size_t)(nbase + nc + r) * DH + c]);
            *reinterpret_cast<float4*>(&sV[r][c]) =
                *reinterpret_cast<const float4*>(&Vp[(size_t)(nbase + nc + r) * DH + c]);
        }
        __syncthreads();
#pragma unroll
        for (int nn = 0; nn < 32; nn++) {
            float4 rk = *reinterpret_cast<const float4*>(&sK[nn][d1b]);
            float4 rv = *reinterpret_cast<const float4*>(&sV[nn][d2b]);
            float k[4] = {rk.x, rk.y, rk.z, rk.w};
            float v[4] = {rv.x, rv.y, rv.z, rv.w};
#pragma unroll
            for (int i = 0; i < 4; i++)
#pragma unroll
                for (int j = 0; j < 4; j++) acc[i][j] += k[i] * v[j];
        }
        __syncthreads();
    }

    float* dst = &g_ktv_part[(size_t)split * (HEADS * DH * DH) + (size_t)h * DH * DH];
#pragma unroll
    for (int i = 0; i < 4; i++) {
        float4 v = {acc[i][0], acc[i][1], acc[i][2], acc[i][3]};
        *reinterpret_cast<float4*>(&dst[(d1b + i) * DH + d2b]) = v;
    }
}

__global__ void ktv_reduce() {
    int i = blockIdx.x * 256 + threadIdx.x;   // 32768 entries
    float s = 0.f;
#pragma unroll
    for (int sp = 0; sp < 16; sp++) s += g_ktv_part[(size_t)sp * (HEADS * DH * DH) + i];
    g_ktv[i] = s;
}

// ---------------------------------------------------------------------------
// Kernel 4: per row n:  out[h][n][:] = SCALE * q[n] @ KtV[h]
//                       coarse[h][n] = SCALE * dot(k[n], qsum[h])
// grid (8 heads, 16 tiles of 256 rows), 256 threads = 1 row/thread
// ---------------------------------------------------------------------------
__global__ __launch_bounds__(256) void out_kernel(float* __restrict__ coarse,
                                                  float* __restrict__ out) {
    int h = blockIdx.x;
    int nt = blockIdx.y;
    int tid = threadIdx.x;
    int n = nt * 256 + tid;

    __shared__ float sM[DH * DH];
    __shared__ float sQs[DH];
#pragma unroll
    for (int i = 0; i < 4; i++) {
        int lin = tid + i * 256;   // 1024 float4s total
        *reinterpret_cast<float4*>(&sM[lin * 4]) =
            *reinterpret_cast<const float4*>(&g_ktv[(size_t)h * DH * DH + lin * 4]);
    }
    if (tid < 64) sQs[tid] = g_qsum[h * 64 + tid];
    __syncthreads();

    const float* Qr = &g_qkv[(size_t)h * HSTRIDE + (size_t)n * DH];
    const float* Kr = &g_qkv[(size_t)1 * PSTRIDE + (size_t)h * HSTRIDE + (size_t)n * DH];

    float qr[64];
    float cacc = 0.f;
#pragma unroll
    for (int d4 = 0; d4 < 64; d4 += 4) {
        float4 q4 = *reinterpret_cast<const float4*>(&Qr[d4]);
        qr[d4] = q4.x; qr[d4 + 1] = q4.y; qr[d4 + 2] = q4.z; qr[d4 + 3] = q4.w;
        float4 k4 = *reinterpret_cast<const float4*>(&Kr[d4]);
        cacc += k4.x * sQs[d4] + k4.y * sQs[d4 + 1] + k4.z * sQs[d4 + 2] + k4.w * sQs[d4 + 3];
    }
    coarse[h * TOK + n] = cacc * SCALE;

    float* op = &out[((size_t)h * TOK + n) * DH];
#pragma unroll
    for (int d2 = 0; d2 < 64; d2 += 4) {
        float a0 = 0.f, a1 = 0.f, a2 = 0.f, a3 = 0.f;
#pragma unroll
        for (int d1 = 0; d1 < 64; d1++) {
            float4 m4 = *reinterpret_cast<const float4*>(&sM[d1 * 64 + d2]);
            float q = qr[d1];
            a0 += q * m4.x; a1 += q * m4.y; a2 += q * m4.z; a3 += q * m4.w;
        }
        float4 v = {a0 * SCALE, a1 * SCALE, a2 * SCALE, a3 * SCALE};
        *reinterpret_cast<float4*>(&op[d2]) = v;
    }
}

// ---------------------------------------------------------------------------
extern "C" void kernel_launch(void* const* d_in, const int* in_sizes, int n_in,
                              void* d_out, int out_size) {
    const float* x = (const float*)d_in[0];   // [512, 4096] (E-major)
    const float* W = (const float*)d_in[1];   // [512, 1536]
    const float* b = (const float*)d_in[2];   // [1536]

    float* coarse = (float*)d_out;                       // [8, 4096]
    float* out    = (float*)d_out + HEADS * TOK;         // [8, 4096, 64]

    qkv_gemm<<<dim3(QKVN / BN, TOK / BM), 256>>>(x, W, b);
    qsum_kernel<<<HEADS, 256>>>();
    ktv_kernel<<<dim3(HEADS, 16), 256>>>();
    ktv_reduce<<<128, 256>>>();
    out_kernel<<<dim3(HEADS, 16), 256>>>(coarse, out);
}

// round 3
// speedup vs baseline: 1.0685x; 1.0685x over previous
#include <cuda_runtime.h>
#include <cuda_bf16.h>
#include <cstdint>

#define TOK   4096
#define EMB   512
#define QKVN  1536
#define HEADS 8
#define DH    64
#define SCALE 0.125f

#define HSTRIDE (TOK * DH)           // 262144
#define PSTRIDE (HEADS * TOK * DH)   // 2097152

// ---------------- scratch (device globals) ----------------
__device__ float g_qkv[3 * HEADS * TOK * DH];        // [part][h][n][d]
__device__ float g_qsum[HEADS * DH];
__device__ float g_ktv[HEADS * DH * DH];
__device__ float g_ktv_part[16 * HEADS * DH * DH];

__device__ __nv_bfloat16 g_a_hi[TOK * EMB];          // A = x^T  [4096, 512]
__device__ __nv_bfloat16 g_a_lo[TOK * EMB];
__device__ __nv_bfloat16 g_b_hi[QKVN * EMB];         // B = W^T  [1536, 512]
__device__ __nv_bfloat16 g_b_lo[QKVN * EMB];

// ---------------- helpers ----------------
__device__ __forceinline__ uint32_t smem_u32(const void* p) {
    uint32_t a;
    asm("{ .reg .u64 t; cvta.to.shared.u64 t, %1; cvt.u32.u64 %0, t; }" : "=r"(a) : "l"(p));
    return a;
}
__device__ __forceinline__ uint32_t lds32(uint32_t a) {
    uint32_t v;
    asm volatile("ld.shared.b32 %0, [%1];" : "=r"(v) : "r"(a));
    return v;
}
__device__ __forceinline__ void cp_async16(uint32_t saddr, const void* gaddr) {
    asm volatile("cp.async.cg.shared.global [%0], [%1], 16;" :: "r"(saddr), "l"(gaddr));
}
__device__ __forceinline__ void cp_commit() { asm volatile("cp.async.commit_group;"); }
__device__ __forceinline__ void cp_wait1()  { asm volatile("cp.async.wait_group 1;"); }
__device__ __forceinline__ void cp_wait0()  { asm volatile("cp.async.wait_group 0;"); }

__device__ __forceinline__ void mma_bf16(float& c0, float& c1, float& c2, float& c3,
                                         uint32_t a0, uint32_t a1, uint32_t a2, uint32_t a3,
                                         uint32_t b0, uint32_t b1) {
    asm volatile(
        "mma.sync.aligned.m16n8k16.row.col.f32.bf16.bf16.f32 "
        "{%0,%1,%2,%3}, {%4,%5,%6,%7}, {%8,%9}, {%0,%1,%2,%3};"
        : "+f"(c0), "+f"(c1), "+f"(c2), "+f"(c3)
        : "r"(a0), "r"(a1), "r"(a2), "r"(a3), "r"(b0), "r"(b1));
}

// ---------------------------------------------------------------------------
// Pre-pass: split-transpose  src[512, Mcols] f32 -> dhi/dlo [Mcols, 512] bf16
// ---------------------------------------------------------------------------
__global__ __launch_bounds__(256) void split_transpose(const float* __restrict__ src,
                                                       __nv_bfloat16* __restrict__ dhi,
                                                       __nv_bfloat16* __restrict__ dlo,
                                                       int Mcols) {
    __shared__ float tile[32][33];
    int tx = threadIdx.x & 31, ty = threadIdx.x >> 5;
    int m0 = blockIdx.x * 32, k0 = blockIdx.y * 32;
#pragma unroll
    for (int j = 0; j < 4; j++)
        tile[ty + j * 8][tx] = src[(size_t)(k0 + ty + j * 8) * Mcols + m0 + tx];
    __syncthreads();
#pragma unroll
    for (int j = 0; j < 4; j++) {
        int m = m0 + ty + j * 8;
        float v = tile[tx][ty + j * 8];
        __nv_bfloat16 hi = __float2bfloat16(v);
        float r = v - __bfloat162float(hi);
        dhi[(size_t)m * EMB + k0 + tx] = hi;
        dlo[(size_t)m * EMB + k0 + tx] = __float2bfloat16(r);
    }
}

// ---------------------------------------------------------------------------
// mma.sync QKV GEMM: D[m, o] = sum_k A[m,k]*B[o,k] + bias[o]
// block 128x128, BK=32, bf16 3-pass split, cp.async double buffer.
// smem rows padded to 40 halves (80 B) -> fragment loads are bank-conflict-free.
// ---------------------------------------------------------------------------
#define GBM 128
#define GBN 128
#define GBK 32
#define ROWB   80                  // bytes per smem row
#define TILE_B (128 * ROWB)        // 10240 B per tile
#define T_AHI  0
#define T_ALO  (1 * TILE_B)
#define T_BHI  (2 * TILE_B)
#define T_BLO  (3 * TILE_B)
#define STG_B  (4 * TILE_B)        // 40960 per stage
#define SM_BIAS (2 * STG_B)        // 81920
#define SM_TOT  (SM_BIAS + 512)

__global__ void __launch_bounds__(256, 1) qkv_gemm_mma(const float* __restrict__ bias) {
    extern __shared__ char smem[];
    const uint32_t sb = smem_u32(smem);
    const int tid  = threadIdx.x;
    const int wid  = tid >> 5;
    const int lane = tid & 31;
    const int g    = lane >> 2;        // 0..7
    const int tg   = lane & 3;         // 0..3
    const int wm   = wid >> 2;         // 0..1  (64-row slab)
    const int wn   = wid & 3;          // 0..3  (32-col slab)
    const int o0   = blockIdx.x * GBN;
    const int m0   = blockIdx.y * GBM;

    if (tid < 128) *reinterpret_cast<float*>(smem + SM_BIAS + tid * 4) = bias[o0 + tid];

    const __nv_bfloat16* srcs[4] = {
        &g_a_hi[(size_t)m0 * EMB], &g_a_lo[(size_t)m0 * EMB],
        &g_b_hi[(size_t)o0 * EMB], &g_b_lo[(size_t)o0 * EMB]};

    // issue one k-chunk's gmem->smem copies (4 tiles x 512 float4 / 256 thr)
    auto issue = [&](int chunk) {
        const int kt = chunk * GBK;
        const uint32_t stage = sb + (chunk & 1) * STG_B;
#pragma unroll
        for (int t = 0; t < 4; t++) {
            const __nv_bfloat16* gp = srcs[t] + kt;
            const uint32_t tb = stage + t * TILE_B;
#pragma unroll
            for (int i = 0; i < 2; i++) {
                int lin = tid + i * 256;          // 0..511
                int row = lin >> 2;
                int seg = lin & 3;
                cp_async16(tb + row * ROWB + seg * 16, gp + (size_t)row * EMB + seg * 8);
            }
        }
        cp_commit();
    };

    float acc[4][4][4];
#pragma unroll
    for (int i = 0; i < 4; i++)
#pragma unroll
        for (int j = 0; j < 4; j++)
#pragma unroll
            for (int c = 0; c < 4; c++) acc[i][j][c] = 0.f;

    issue(0);

    const uint32_t aRow0 = wm * 64 + g;          // row within A tile for this lane
    const uint32_t bRow0 = wn * 32 + g;          // row within B tile

    for (int chunk = 0; chunk < EMB / GBK; ++chunk) {
        if (chunk + 1 < EMB / GBK) { issue(chunk + 1); cp_wait1(); }
        else                       { cp_wait0(); }
        __syncthreads();

        const uint32_t stage = sb + (chunk & 1) * STG_B;

#pragma unroll
        for (int kk = 0; kk < 2; kk++) {          // two k16 steps per chunk
            const uint32_t klo = kk * 32 + tg * 4;  // byte offset of k pair

            uint32_t ahi[4][4], alo[4][4], bhi[4][2], blo[4][2];
#pragma unroll
            for (int mt = 0; mt < 4; mt++) {
                uint32_t base = stage + (aRow0 + mt * 16) * ROWB + klo;
                ahi[mt][0] = lds32(base + T_AHI);
                ahi[mt][1] = lds32(base + T_AHI + 8 * ROWB);
                ahi[mt][2] = lds32(base + T_AHI + 16);
                ahi[mt][3] = lds32(base + T_AHI + 8 * ROWB + 16);
                alo[mt][0] = lds32(base + T_ALO);
                alo[mt][1] = lds32(base + T_ALO + 8 * ROWB);
                alo[mt][2] = lds32(base + T_ALO + 16);
                alo[mt][3] = lds32(base + T_ALO + 8 * ROWB + 16);
            }
#pragma unroll
            for (int nt = 0; nt < 4; nt++) {
                uint32_t base = stage + (bRow0 + nt * 8) * ROWB + klo;
                bhi[nt][0] = lds32(base + T_BHI);
                bhi[nt][1] = lds32(base + T_BHI + 16);
                blo[nt][0] = lds32(base + T_BLO);
                blo[nt][1] = lds32(base + T_BLO + 16);
            }

#pragma unroll
            for (int mt = 0; mt < 4; mt++)
#pragma unroll
                for (int nt = 0; nt < 4; nt++) {
                    float* c = acc[mt][nt];
                    mma_bf16(c[0], c[1], c[2], c[3],
                             ahi[mt][0], ahi[mt][1], ahi[mt][2], ahi[mt][3],
                             bhi[nt][0], bhi[nt][1]);
                    mma_bf16(c[0], c[1], c[2], c[3],
                             ahi[mt][0], ahi[mt][1], ahi[mt][2], ahi[mt][3],
                             blo[nt][0], blo[nt][1]);
                    mma_bf16(c[0], c[1], c[2], c[3],
                             alo[mt][0], alo[mt][1], alo[mt][2], alo[mt][3],
                             bhi[nt][0], bhi[nt][1]);
                }
        }
        __syncthreads();
    }

    // epilogue: add bias, scatter to g_qkv [part][h][n][d]
    const float* sbias = reinterpret_cast<const float*>(smem + SM_BIAS);
#pragma unroll
    for (int mt = 0; mt < 4; mt++) {
        const int m = m0 + wm * 64 + mt * 16 + g;
#pragma unroll
        for (int nt = 0; nt < 4; nt++) {
            const int off = wn * 32 + nt * 8 + 2 * tg;   // 0..127
            const int o = o0 + off;
            const int part = o >> 9;
            const int h = (o >> 6) & 7;
            const int d = o & 63;
            const float bv0 = sbias[off], bv1 = sbias[off + 1];
            float* base = &g_qkv[(size_t)part * PSTRIDE + (size_t)h * HSTRIDE];
            float2 r0 = {acc[mt][nt][0] + bv0, acc[mt][nt][1] + bv1};
            float2 r1 = {acc[mt][nt][2] + bv0, acc[mt][nt][3] + bv1};
            *reinterpret_cast<float2*>(&base[(size_t)m * DH + d]) = r0;
            *reinterpret_cast<float2*>(&base[(size_t)(m + 8) * DH + d]) = r1;
        }
    }
}

// ---------------------------------------------------------------------------
// qsum[h][d] = sum_n Q[h][n][d]
// ---------------------------------------------------------------------------
__global__ __launch_bounds__(256) void qsum_kernel() {
    int h = blockIdx.x;
    int tid = threadIdx.x;
    int d = tid & 63;
    int s = tid >> 6;
    const float* Q = &g_qkv[(size_t)h * HSTRIDE];
    float sum = 0.f;
    for (int n = s; n < TOK; n += 4) sum += Q[(size_t)n * DH + d];
    __shared__ float red[4][64];
    red[s][d] = sum;
    __syncthreads();
    if (tid < 64)
        g_qsum[h * 64 + tid] = red[0][tid] + red[1][tid] + red[2][tid] + red[3][tid];
}

// ---------------------------------------------------------------------------
// partial KtV over N splits (deterministic)
// ---------------------------------------------------------------------------
__global__ __launch_bounds__(256) void ktv_kernel() {
    int h = blockIdx.x;
    int split = blockIdx.y;
    const float* Kp = &g_qkv[(size_t)1 * PSTRIDE + (size_t)h * HSTRIDE];
    const float* Vp = &g_qkv[(size_t)2 * PSTRIDE + (size_t)h * HSTRIDE];

    __shared__ float sK[32][64];
    __shared__ float sV[32][64];

    int tid = threadIdx.x;
    int d1b = (tid >> 4) << 2;
    int d2b = (tid & 15) << 2;
    float acc[4][4];
#pragma unroll
    for (int i = 0; i < 4; i++)
#pragma unroll
        for (int j = 0; j < 4; j++) acc[i][j] = 0.f;

    int nbase = split * 256;
    for (int nc = 0; nc < 256; nc += 32) {
#pragma unroll
        for (int i = 0; i < 2; i++) {
            int lin = tid + i * 256;
            int r = lin >> 4;
            int c = (lin & 15) << 2;
            *reinterpret_cast<float4*>(&sK[r][c]) =
                *reinterpret_cast<const float4*>(&Kp[(size_t)(nbase + nc + r) * DH + c]);
            *reinterpret_cast<float4*>(&sV[r][c]) =
                *reinterpret_cast<const float4*>(&Vp[(size_t)(nbase + nc + r) * DH + c]);
        }
        __syncthreads();
#pragma unroll
        for (int nn = 0; nn < 32; nn++) {
            float4 rk = *reinterpret_cast<const float4*>(&sK[nn][d1b]);
            float4 rv = *reinterpret_cast<const float4*>(&sV[nn][d2b]);
            float k[4] = {rk.x, rk.y, rk.z, rk.w};
            float v[4] = {rv.x, rv.y, rv.z, rv.w};
#pragma unroll
            for (int i = 0; i < 4; i++)
#pragma unroll
                for (int j = 0; j < 4; j++) acc[i][j] += k[i] * v[j];
        }
        __syncthreads();
    }

    float* dst = &g_ktv_part[(size_t)split * (HEADS * DH * DH) + (size_t)h * DH * DH];
#pragma unroll
    for (int i = 0; i < 4; i++) {
        float4 v = {acc[i][0], acc[i][1], acc[i][2], acc[i][3]};
        *reinterpret_cast<float4*>(&dst[(d1b + i) * DH + d2b]) = v;
    }
}

__global__ void ktv_reduce() {
    int i = blockIdx.x * 256 + threadIdx.x;
    float s = 0.f;
#pragma unroll
    for (int sp = 0; sp < 16; sp++) s += g_ktv_part[(size_t)sp * (HEADS * DH * DH) + i];
    g_ktv[i] = s;
}

// ---------------------------------------------------------------------------
// out[h][n][:] = SCALE * q[n] @ KtV[h];  coarse[h][n] = SCALE * dot(k[n], qsum[h])
// ---------------------------------------------------------------------------
__global__ __launch_bounds__(256) void out_kernel(float* __restrict__ coarse,
                                                  float* __restrict__ out) {
    int h = blockIdx.x;
    int nt = blockIdx.y;
    int tid = threadIdx.x;
    int n = nt * 256 + tid;

    __shared__ float sM[DH * DH];
    __shared__ float sQs[DH];
#pragma unroll
    for (int i = 0; i < 4; i++) {
        int lin = tid + i * 256;
        *reinterpret_cast<float4*>(&sM[lin * 4]) =
            *reinterpret_cast<const float4*>(&g_ktv[(size_t)h * DH * DH + lin * 4]);
    }
    if (tid < 64) sQs[tid] = g_qsum[h * 64 + tid];
    __syncthreads();

    const float* Qr = &g_qkv[(size_t)h * HSTRIDE + (size_t)n * DH];
    const float* Kr = &g_qkv[(size_t)1 * PSTRIDE + (size_t)h * HSTRIDE + (size_t)n * DH];

    float qr[64];
    float cacc = 0.f;
#pragma unroll
    for (int d4 = 0; d4 < 64; d4 += 4) {
        float4 q4 = *reinterpret_cast<const float4*>(&Qr[d4]);
        qr[d4] = q4.x; qr[d4 + 1] = q4.y; qr[d4 + 2] = q4.z; qr[d4 + 3] = q4.w;
        float4 k4 = *reinterpret_cast<const float4*>(&Kr[d4]);
        cacc += k4.x * sQs[d4] + k4.y * sQs[d4 + 1] + k4.z * sQs[d4 + 2] + k4.w * sQs[d4 + 3];
    }
    coarse[h * TOK + n] = cacc * SCALE;

    float* op = &out[((size_t)h * TOK + n) * DH];
#pragma unroll
    for (int d2 = 0; d2 < 64; d2 += 4) {
        float a0 = 0.f, a1 = 0.f, a2 = 0.f, a3 = 0.f;
#pragma unroll
        for (int d1 = 0; d1 < 64; d1++) {
            float4 m4 = *reinterpret_cast<const float4*>(&sM[d1 * 64 + d2]);
            float q = qr[d1];
            a0 += q * m4.x; a1 += q * m4.y; a2 += q * m4.z; a3 += q * m4.w;
        }
        float4 v = {a0 * SCALE, a1 * SCALE, a2 * SCALE, a3 * SCALE};
        *reinterpret_cast<float4*>(&op[d2]) = v;
    }
}

// ---------------------------------------------------------------------------
extern "C" void kernel_launch(void* const* d_in, const int* in_sizes, int n_in,
                              void* d_out, int out_size) {
    const float* x = (const float*)d_in[0];   // [512, 4096]
    const float* W = (const float*)d_in[1];   // [512, 1536]
    const float* b = (const float*)d_in[2];   // [1536]

    float* coarse = (float*)d_out;
    float* out    = (float*)d_out + HEADS * TOK;

    __nv_bfloat16 *ahi, *alo, *bhi, *blo;
    cudaGetSymbolAddress((void**)&ahi, g_a_hi);
    cudaGetSymbolAddress((void**)&alo, g_a_lo);
    cudaGetSymbolAddress((void**)&bhi, g_b_hi);
    cudaGetSymbolAddress((void**)&blo, g_b_lo);

    cudaFuncSetAttribute(qkv_gemm_mma, cudaFuncAttributeMaxDynamicSharedMemorySize, SM_TOT);

    split_transpose<<<dim3(TOK / 32, EMB / 32), 256>>>(x, ahi, alo, TOK);
    split_transpose<<<dim3(QKVN / 32, EMB / 32), 256>>>(W, bhi, blo, QKVN);

    qkv_gemm_mma<<<dim3(QKVN / GBN, TOK / GBM), 256, SM_TOT>>>(b);

    qsum_kernel<<<HEADS, 256>>>();
    ktv_kernel<<<dim3(HEADS, 16), 256>>>();
    ktv_reduce<<<128, 256>>>();
    out_kernel<<<dim3(HEADS, 16), 256>>>(coarse, out);
}

// round 4
// speedup vs baseline: 1.9921x; 1.8644x over previous
#include <cuda_runtime.h>
#include <cuda_bf16.h>
#include <cstdint>

#define TOK   4096
#define EMB   512
#define QKVN  1536
#define HEADS 8
#define DH    64
#define SCALE 0.125f

#define HSTRIDE (TOK * DH)           // 262144
#define PSTRIDE (HEADS * TOK * DH)   // 2097152

// ---------------- scratch (device globals) ----------------
__device__ float g_qkv[3 * HEADS * TOK * DH];        // [part][h][n][d]
__device__ float g_qsum[HEADS * DH];
__device__ float g_qsum_part[32 * HEADS * DH];
__device__ float g_ktv[HEADS * DH * DH];
__device__ float g_ktv_part[32 * HEADS * DH * DH];

__device__ __nv_bfloat16 g_a_hi[TOK * EMB];          // A = x^T  [4096, 512]
__device__ __nv_bfloat16 g_a_lo[TOK * EMB];
__device__ __nv_bfloat16 g_b_hi[QKVN * EMB];         // B = W^T  [1536, 512]
__device__ __nv_bfloat16 g_b_lo[QKVN * EMB];

// ---------------- helpers ----------------
__device__ __forceinline__ uint32_t smem_u32(const void* p) {
    uint32_t a;
    asm("{ .reg .u64 t; cvta.to.shared.u64 t, %1; cvt.u32.u64 %0, t; }" : "=r"(a) : "l"(p));
    return a;
}
__device__ __forceinline__ uint32_t lds32(uint32_t a) {
    uint32_t v;
    asm volatile("ld.shared.b32 %0, [%1];" : "=r"(v) : "r"(a));
    return v;
}
__device__ __forceinline__ void cp_async16(uint32_t saddr, const void* gaddr) {
    asm volatile("cp.async.cg.shared.global [%0], [%1], 16;" :: "r"(saddr), "l"(gaddr));
}
__device__ __forceinline__ void cp_commit() { asm volatile("cp.async.commit_group;"); }
__device__ __forceinline__ void cp_wait1()  { asm volatile("cp.async.wait_group 1;"); }
__device__ __forceinline__ void cp_wait0()  { asm volatile("cp.async.wait_group 0;"); }

__device__ __forceinline__ void mma_bf16(float& c0, float& c1, float& c2, float& c3,
                                         uint32_t a0, uint32_t a1, uint32_t a2, uint32_t a3,
                                         uint32_t b0, uint32_t b1) {
    asm volatile(
        "mma.sync.aligned.m16n8k16.row.col.f32.bf16.bf16.f32 "
        "{%0,%1,%2,%3}, {%4,%5,%6,%7}, {%8,%9}, {%0,%1,%2,%3};"
        : "+f"(c0), "+f"(c1), "+f"(c2), "+f"(c3)
        : "r"(a0), "r"(a1), "r"(a2), "r"(a3), "r"(b0), "r"(b1));
}

// ---------------------------------------------------------------------------
// Pre-pass: split-transpose  src[512, Mcols] f32 -> dhi/dlo [Mcols, 512] bf16
// ---------------------------------------------------------------------------
__global__ __launch_bounds__(256) void split_transpose(const float* __restrict__ src,
                                                       __nv_bfloat16* __restrict__ dhi,
                                                       __nv_bfloat16* __restrict__ dlo,
                                                       int Mcols) {
    __shared__ float tile[32][33];
    int tx = threadIdx.x & 31, ty = threadIdx.x >> 5;
    int m0 = blockIdx.x * 32, k0 = blockIdx.y * 32;
#pragma unroll
    for (int j = 0; j < 4; j++)
        tile[ty + j * 8][tx] = src[(size_t)(k0 + ty + j * 8) * Mcols + m0 + tx];
    __syncthreads();
#pragma unroll
    for (int j = 0; j < 4; j++) {
        int m = m0 + ty + j * 8;
        float v = tile[tx][ty + j * 8];
        __nv_bfloat16 hi = __float2bfloat16(v);
        float r = v - __bfloat162float(hi);
        dhi[(size_t)m * EMB + k0 + tx] = hi;
        dlo[(size_t)m * EMB + k0 + tx] = __float2bfloat16(r);
    }
}

// ---------------------------------------------------------------------------
// mma.sync QKV GEMM: D[m, o] = sum_k A[m,k]*B[o,k] + bias[o]
// block 128x128, BK=32, bf16 3-pass split, cp.async double buffer, occ 2.
// ---------------------------------------------------------------------------
#define GBM 128
#define GBN 128
#define GBK 32
#define ROWB   80                  // bytes per smem row (40 halves, conflict-free)
#define TILE_B (128 * ROWB)        // 10240 B per tile
#define T_AHI  0
#define T_ALO  (1 * TILE_B)
#define T_BHI  (2 * TILE_B)
#define T_BLO  (3 * TILE_B)
#define STG_B  (4 * TILE_B)        // 40960 per stage
#define SM_BIAS (2 * STG_B)        // 81920
#define SM_TOT  (SM_BIAS + 512)

__global__ void __launch_bounds__(256, 2) qkv_gemm_mma(const float* __restrict__ bias) {
    extern __shared__ char smem[];
    const uint32_t sb = smem_u32(smem);
    const int tid  = threadIdx.x;
    const int wid  = tid >> 5;
    const int lane = tid & 31;
    const int g    = lane >> 2;        // 0..7
    const int tg   = lane & 3;         // 0..3
    const int wm   = wid >> 2;         // 0..1  (64-row slab)
    const int wn   = wid & 3;          // 0..3  (32-col slab)
    const int o0   = blockIdx.x * GBN;
    const int m0   = blockIdx.y * GBM;

    if (tid < 128) *reinterpret_cast<float*>(smem + SM_BIAS + tid * 4) = bias[o0 + tid];

    const __nv_bfloat16* srcs[4] = {
        &g_a_hi[(size_t)m0 * EMB], &g_a_lo[(size_t)m0 * EMB],
        &g_b_hi[(size_t)o0 * EMB], &g_b_lo[(size_t)o0 * EMB]};

    auto issue = [&](int chunk) {
        const int kt = chunk * GBK;
        const uint32_t stage = sb + (chunk & 1) * STG_B;
#pragma unroll
        for (int t = 0; t < 4; t++) {
            const __nv_bfloat16* gp = srcs[t] + kt;
            const uint32_t tb = stage + t * TILE_B;
#pragma unroll
            for (int i = 0; i < 2; i++) {
                int lin = tid + i * 256;          // 0..511
                int row = lin >> 2;
                int seg = lin & 3;
                cp_async16(tb + row * ROWB + seg * 16, gp + (size_t)row * EMB + seg * 8);
            }
        }
        cp_commit();
    };

    float acc[4][4][4];
#pragma unroll
    for (int i = 0; i < 4; i++)
#pragma unroll
        for (int j = 0; j < 4; j++)
#pragma unroll
            for (int c = 0; c < 4; c++) acc[i][j][c] = 0.f;

    issue(0);

    const uint32_t aRow0 = wm * 64 + g;
    const uint32_t bRow0 = wn * 32 + g;

    for (int chunk = 0; chunk < EMB / GBK; ++chunk) {
        if (chunk + 1 < EMB / GBK) { issue(chunk + 1); cp_wait1(); }
        else                       { cp_wait0(); }
        __syncthreads();

        const uint32_t stage = sb + (chunk & 1) * STG_B;

#pragma unroll
        for (int kk = 0; kk < 2; kk++) {
            const uint32_t klo = kk * 32 + tg * 4;

            // pass 1: Ahi x Bhi
            uint32_t ahi[4][4], bfr[4][2];
#pragma unroll
            for (int mt = 0; mt < 4; mt++) {
                uint32_t base = stage + (aRow0 + mt * 16) * ROWB + klo + T_AHI;
                ahi[mt][0] = lds32(base);
                ahi[mt][1] = lds32(base + 8 * ROWB);
                ahi[mt][2] = lds32(base + 16);
                ahi[mt][3] = lds32(base + 8 * ROWB + 16);
            }
#pragma unroll
            for (int nt = 0; nt < 4; nt++) {
                uint32_t base = stage + (bRow0 + nt * 8) * ROWB + klo + T_BHI;
                bfr[nt][0] = lds32(base);
                bfr[nt][1] = lds32(base + 16);
            }
#pragma unroll
            for (int mt = 0; mt < 4; mt++)
#pragma unroll
                for (int nt = 0; nt < 4; nt++)
                    mma_bf16(acc[mt][nt][0], acc[mt][nt][1], acc[mt][nt][2], acc[mt][nt][3],
                             ahi[mt][0], ahi[mt][1], ahi[mt][2], ahi[mt][3],
                             bfr[nt][0], bfr[nt][1]);

            // pass 2: Alo x Bhi (reuse bfr)
            uint32_t alo[4][4];
#pragma unroll
            for (int mt = 0; mt < 4; mt++) {
                uint32_t base = stage + (aRow0 + mt * 16) * ROWB + klo + T_ALO;
                alo[mt][0] = lds32(base);
                alo[mt][1] = lds32(base + 8 * ROWB);
                alo[mt][2] = lds32(base + 16);
                alo[mt][3] = lds32(base + 8 * ROWB + 16);
            }
#pragma unroll
            for (int mt = 0; mt < 4; mt++)
#pragma unroll
                for (int nt = 0; nt < 4; nt++)
                    mma_bf16(acc[mt][nt][0], acc[mt][nt][1], acc[mt][nt][2], acc[mt][nt][3],
                             alo[mt][0], alo[mt][1], alo[mt][2], alo[mt][3],
                             bfr[nt][0], bfr[nt][1]);

            // pass 3: Ahi x Blo (overwrite bfr)
#pragma unroll
            for (int nt = 0; nt < 4; nt++) {
                uint32_t base = stage + (bRow0 + nt * 8) * ROWB + klo + T_BLO;
                bfr[nt][0] = lds32(base);
                bfr[nt][1] = lds32(base + 16);
            }
#pragma unroll
            for (int mt = 0; mt < 4; mt++)
#pragma unroll
                for (int nt = 0; nt < 4; nt++)
                    mma_bf16(acc[mt][nt][0], acc[mt][nt][1], acc[mt][nt][2], acc[mt][nt][3],
                             ahi[mt][0], ahi[mt][1], ahi[mt][2], ahi[mt][3],
                             bfr[nt][0], bfr[nt][1]);
        }
        __syncthreads();
    }

    // epilogue: add bias, scatter to g_qkv [part][h][n][d]
    const float* sbias = reinterpret_cast<const float*>(smem + SM_BIAS);
#pragma unroll
    for (int mt = 0; mt < 4; mt++) {
        const int m = m0 + wm * 64 + mt * 16 + g;
#pragma unroll
        for (int nt = 0; nt < 4; nt++) {
            const int off = wn * 32 + nt * 8 + 2 * tg;
            const int o = o0 + off;
            const int part = o >> 9;
            const int h = (o >> 6) & 7;
            const int d = o & 63;
            const float bv0 = sbias[off], bv1 = sbias[off + 1];
            float* base = &g_qkv[(size_t)part * PSTRIDE + (size_t)h * HSTRIDE];
            float2 r0 = {acc[mt][nt][0] + bv0, acc[mt][nt][1] + bv1};
            float2 r1 = {acc[mt][nt][2] + bv0, acc[mt][nt][3] + bv1};
            *reinterpret_cast<float2*>(&base[(size_t)m * DH + d]) = r0;
            *reinterpret_cast<float2*>(&base[(size_t)(m + 8) * DH + d]) = r1;
        }
    }
}

// ---------------------------------------------------------------------------
// qsum: split partials over (8 heads, 32 splits), then reduce
// ---------------------------------------------------------------------------
__global__ __launch_bounds__(256) void qsum_part_kernel() {
    int h = blockIdx.x;
    int split = blockIdx.y;
    int tid = threadIdx.x;
    int d = tid & 63;
    int s = tid >> 6;
    const float* Q = &g_qkv[(size_t)h * HSTRIDE + (size_t)split * 128 * DH];
    float sum = 0.f;
#pragma unroll
    for (int n = s; n < 128; n += 4) sum += Q[(size_t)n * DH + d];
    __shared__ float red[4][64];
    red[s][d] = sum;
    __syncthreads();
    if (tid < 64)
        g_qsum_part[(split * HEADS + h) * 64 + tid] =
            red[0][tid] + red[1][tid] + red[2][tid] + red[3][tid];
}

__global__ __launch_bounds__(512) void qsum_reduce_kernel() {
    int i = threadIdx.x;       // h*64+d, 512 entries
    float s = 0.f;
#pragma unroll
    for (int sp = 0; sp < 32; sp++) s += g_qsum_part[sp * (HEADS * 64) + i];
    g_qsum[i] = s;
}

// ---------------------------------------------------------------------------
// partial KtV over 32 N-splits (deterministic)
// ---------------------------------------------------------------------------
__global__ __launch_bounds__(256) void ktv_kernel() {
    int h = blockIdx.x;
    int split = blockIdx.y;
    const float* Kp = &g_qkv[(size_t)1 * PSTRIDE + (size_t)h * HSTRIDE];
    const float* Vp = &g_qkv[(size_t)2 * PSTRIDE + (size_t)h * HSTRIDE];

    __shared__ float sK[32][64];
    __shared__ float sV[32][64];

    int tid = threadIdx.x;
    int d1b = (tid >> 4) << 2;
    int d2b = (tid & 15) << 2;
    float acc[4][4];
#pragma unroll
    for (int i = 0; i < 4; i++)
#pragma unroll
        for (int j = 0; j < 4; j++) acc[i][j] = 0.f;

    int nbase = split * 128;
    for (int nc = 0; nc < 128; nc += 32) {
#pragma unroll
        for (int i = 0; i < 2; i++) {
            int lin = tid + i * 256;
            int r = lin >> 4;
            int c = (lin & 15) << 2;
            *reinterpret_cast<float4*>(&sK[r][c]) =
                *reinterpret_cast<const float4*>(&Kp[(size_t)(nbase + nc + r) * DH + c]);
            *reinterpret_cast<float4*>(&sV[r][c]) =
                *reinterpret_cast<const float4*>(&Vp[(size_t)(nbase + nc + r) * DH + c]);
        }
        __syncthreads();
#pragma unroll
        for (int nn = 0; nn < 32; nn++) {
            float4 rk = *reinterpret_cast<const float4*>(&sK[nn][d1b]);
            float4 rv = *reinterpret_cast<const float4*>(&sV[nn][d2b]);
            float k[4] = {rk.x, rk.y, rk.z, rk.w};
            float v[4] = {rv.x, rv.y, rv.z, rv.w};
#pragma unroll
            for (int i = 0; i < 4; i++)
#pragma unroll
                for (int j = 0; j < 4; j++) acc[i][j] += k[i] * v[j];
        }
        __syncthreads();
    }

    float* dst = &g_ktv_part[(size_t)split * (HEADS * DH * DH) + (size_t)h * DH * DH];
#pragma unroll
    for (int i = 0; i < 4; i++) {
        float4 v = {acc[i][0], acc[i][1], acc[i][2], acc[i][3]};
        *reinterpret_cast<float4*>(&dst[(d1b + i) * DH + d2b]) = v;
    }
}

__global__ void ktv_reduce() {
    int i = blockIdx.x * 256 + threadIdx.x;
    float s = 0.f;
#pragma unroll
    for (int sp = 0; sp < 32; sp++) s += g_ktv_part[(size_t)sp * (HEADS * DH * DH) + i];
    g_ktv[i] = s;
}

// ---------------------------------------------------------------------------
// out[h][n][:] = SCALE * q[n] @ KtV[h];  coarse[h][n] = SCALE * dot(k[n], qsum[h])
// grid (8, 32), 128 threads, 1 row/thread
// ---------------------------------------------------------------------------
__global__ __launch_bounds__(128) void out_kernel(float* __restrict__ coarse,
                                                  float* __restrict__ out) {
    int h = blockIdx.x;
    int nt = blockIdx.y;
    int tid = threadIdx.x;
    int n = nt * 128 + tid;

    __shared__ float sM[DH * DH];
    __shared__ float sQs[DH];
#pragma unroll
    for (int i = 0; i < 8; i++) {
        int lin = tid + i * 128;
        *reinterpret_cast<float4*>(&sM[lin * 4]) =
            *reinterpret_cast<const float4*>(&g_ktv[(size_t)h * DH * DH + lin * 4]);
    }
    if (tid < 64) sQs[tid] = g_qsum[h * 64 + tid];
    __syncthreads();

    const float* Qr = &g_qkv[(size_t)h * HSTRIDE + (size_t)n * DH];
    const float* Kr = &g_qkv[(size_t)1 * PSTRIDE + (size_t)h * HSTRIDE + (size_t)n * DH];

    float qr[64];
    float cacc = 0.f;
#pragma unroll
    for (int d4 = 0; d4 < 64; d4 += 4) {
        float4 q4 = *reinterpret_cast<const float4*>(&Qr[d4]);
        qr[d4] = q4.x; qr[d4 + 1] = q4.y; qr[d4 + 2] = q4.z; qr[d4 + 3] = q4.w;
        float4 k4 = *reinterpret_cast<const float4*>(&Kr[d4]);
        cacc += k4.x * sQs[d4] + k4.y * sQs[d4 + 1] + k4.z * sQs[d4 + 2] + k4.w * sQs[d4 + 3];
    }
    coarse[h * TOK + n] = cacc * SCALE;

    float* op = &out[((size_t)h * TOK + n) * DH];
#pragma unroll
    for (int d2 = 0; d2 < 64; d2 += 4) {
        float a0 = 0.f, a1 = 0.f, a2 = 0.f, a3 = 0.f;
#pragma unroll
        for (int d1 = 0; d1 < 64; d1++) {
            float4 m4 = *reinterpret_cast<const float4*>(&sM[d1 * 64 + d2]);
            float q = qr[d1];
            a0 += q * m4.x; a1 += q * m4.y; a2 += q * m4.z; a3 += q * m4.w;
        }
        float4 v = {a0 * SCALE, a1 * SCALE, a2 * SCALE, a3 * SCALE};
        *reinterpret_cast<float4*>(&op[d2]) = v;
    }
}

// ---------------------------------------------------------------------------
extern "C" void kernel_launch(void* const* d_in, const int* in_sizes, int n_in,
                              void* d_out, int out_size) {
    const float* x = (const float*)d_in[0];   // [512, 4096]
    const float* W = (const float*)d_in[1];   // [512, 1536]
    const float* b = (const float*)d_in[2];   // [1536]

    float* coarse = (float*)d_out;
    float* out    = (float*)d_out + HEADS * TOK;

    __nv_bfloat16 *ahi, *alo, *bhi, *blo;
    cudaGetSymbolAddress((void**)&ahi, g_a_hi);
    cudaGetSymbolAddress((void**)&alo, g_a_lo);
    cudaGetSymbolAddress((void**)&bhi, g_b_hi);
    cudaGetSymbolAddress((void**)&blo, g_b_lo);

    cudaFuncSetAttribute(qkv_gemm_mma, cudaFuncAttributeMaxDynamicSharedMemorySize, SM_TOT);

    split_transpose<<<dim3(TOK / 32, EMB / 32), 256>>>(x, ahi, alo, TOK);
    split_transpose<<<dim3(QKVN / 32, EMB / 32), 256>>>(W, bhi, blo, QKVN);

    qkv_gemm_mma<<<dim3(QKVN / GBN, TOK / GBM), 256, SM_TOT>>>(b);

    qsum_part_kernel<<<dim3(HEADS, 32), 256>>>();
    qsum_reduce_kernel<<<1, 512>>>();
    ktv_kernel<<<dim3(HEADS, 32), 256>>>();
    ktv_reduce<<<128, 256>>>();
    out_kernel<<<dim3(HEADS, 32), 128>>>(coarse, out);
}

// round 5
// speedup vs baseline: 2.3898x; 1.1996x over previous
#include <cuda_runtime.h>
#include <cuda_fp16.h>
#include <cstdint>

#define TOK   4096
#define EMB   512
#define QKVN  1536
#define HEADS 8
#define DH    64
#define SCALE 0.125f

#define HSTRIDE (TOK * DH)           // 262144
#define PSTRIDE (HEADS * TOK * DH)   // 2097152

// ---------------- scratch (device globals) ----------------
__device__ float g_qkv[3 * HEADS * TOK * DH];        // [part][h][n][d]
__device__ float g_qsum[HEADS * DH];
__device__ float g_qsum_part[32 * HEADS * DH];       // [m_block][h*64+d]
__device__ float g_ktv[HEADS * DH * DH];
__device__ float g_ktv_part[32 * HEADS * DH * DH];

__device__ __half g_a_hi[TOK * EMB];                 // A = x^T  [4096, 512]
__device__ __half g_a_lo[TOK * EMB];
__device__ __half g_b_hi[QKVN * EMB];                // B = W^T  [1536, 512]

// ---------------- helpers ----------------
__device__ __forceinline__ uint32_t smem_u32(const void* p) {
    uint32_t a;
    asm("{ .reg .u64 t; cvta.to.shared.u64 t, %1; cvt.u32.u64 %0, t; }" : "=r"(a) : "l"(p));
    return a;
}
__device__ __forceinline__ uint32_t lds32(uint32_t a) {
    uint32_t v;
    asm volatile("ld.shared.b32 %0, [%1];" : "=r"(v) : "r"(a));
    return v;
}
__device__ __forceinline__ void cp_async16(uint32_t saddr, const void* gaddr) {
    asm volatile("cp.async.cg.shared.global [%0], [%1], 16;" :: "r"(saddr), "l"(gaddr));
}
__device__ __forceinline__ void cp_commit() { asm volatile("cp.async.commit_group;"); }
__device__ __forceinline__ void cp_wait1()  { asm volatile("cp.async.wait_group 1;"); }
__device__ __forceinline__ void cp_wait0()  { asm volatile("cp.async.wait_group 0;"); }

__device__ __forceinline__ void mma_f16(float& c0, float& c1, float& c2, float& c3,
                                        uint32_t a0, uint32_t a1, uint32_t a2, uint32_t a3,
                                        uint32_t b0, uint32_t b1) {
    asm volatile(
        "mma.sync.aligned.m16n8k16.row.col.f32.f16.f16.f32 "
        "{%0,%1,%2,%3}, {%4,%5,%6,%7}, {%8,%9}, {%0,%1,%2,%3};"
        : "+f"(c0), "+f"(c1), "+f"(c2), "+f"(c3)
        : "r"(a0), "r"(a1), "r"(a2), "r"(a3), "r"(b0), "r"(b1));
}

// ---------------------------------------------------------------------------
// Pre-pass A: split-transpose  x[512, 4096] f32 -> hi/lo [4096, 512] fp16
// ---------------------------------------------------------------------------
__global__ __launch_bounds__(256) void splitA(const float* __restrict__ src,
                                              __half* __restrict__ dhi,
                                              __half* __restrict__ dlo) {
    __shared__ float tile[32][33];
    int tx = threadIdx.x & 31, ty = threadIdx.x >> 5;
    int m0 = blockIdx.x * 32, k0 = blockIdx.y * 32;
#pragma unroll
    for (int j = 0; j < 4; j++)
        tile[ty + j * 8][tx] = src[(size_t)(k0 + ty + j * 8) * TOK + m0 + tx];
    __syncthreads();
#pragma unroll
    for (int j = 0; j < 4; j++) {
        int m = m0 + ty + j * 8;
        float v = tile[tx][ty + j * 8];
        __half hi = __float2half_rn(v);
        float r = v - __half2float(hi);
        dhi[(size_t)m * EMB + k0 + tx] = hi;
        dlo[(size_t)m * EMB + k0 + tx] = __float2half_rn(r);
    }
}

// Pre-pass B: transpose W[512, 1536] f32 -> hi [1536, 512] fp16
__global__ __launch_bounds__(256) void convB(const float* __restrict__ src,
                                             __half* __restrict__ dhi) {
    __shared__ float tile[32][33];
    int tx = threadIdx.x & 31, ty = threadIdx.x >> 5;
    int m0 = blockIdx.x * 32, k0 = blockIdx.y * 32;
#pragma unroll
    for (int j = 0; j < 4; j++)
        tile[ty + j * 8][tx] = src[(size_t)(k0 + ty + j * 8) * QKVN + m0 + tx];
    __syncthreads();
#pragma unroll
    for (int j = 0; j < 4; j++) {
        int m = m0 + ty + j * 8;
        dhi[(size_t)m * EMB + k0 + tx] = __float2half_rn(tile[tx][ty + j * 8]);
    }
}

// ---------------------------------------------------------------------------
// mma.sync QKV GEMM: D[m, o] = sum_k A[m,k]*B[o,k] + bias[o]
// block 128x128, BK=32, fp16 2-pass split (Ahi*Bhi + Alo*Bhi), occ 2.
// q-part blocks also emit per-block column sums -> g_qsum_part.
// ---------------------------------------------------------------------------
#define GBM 128
#define GBN 128
#define GBK 32
#define ROWB   80                  // bytes per smem row (32 halves + pad)
#define TILE_B (128 * ROWB)        // 10240
#define T_AHI  0
#define T_ALO  (1 * TILE_B)
#define T_BHI  (2 * TILE_B)
#define STG_B  (3 * TILE_B)        // 30720
#define SM_BIAS (2 * STG_B)        // 61440
#define SM_QS   (SM_BIAS + 512)    // 61952 (2*128 floats)
#define SM_TOT  (SM_QS + 1024)

__global__ void __launch_bounds__(256, 2) qkv_gemm_mma(const float* __restrict__ bias) {
    extern __shared__ char smem[];
    const uint32_t sb = smem_u32(smem);
    const int tid  = threadIdx.x;
    const int wid  = tid >> 5;
    const int lane = tid & 31;
    const int g    = lane >> 2;
    const int tg   = lane & 3;
    const int wm   = wid >> 2;         // 0..1
    const int wn   = wid & 3;          // 0..3
    const int o0   = blockIdx.x * GBN;
    const int m0   = blockIdx.y * GBM;

    if (tid < 128) *reinterpret_cast<float*>(smem + SM_BIAS + tid * 4) = bias[o0 + tid];

    const __half* srcs[3] = {
        &g_a_hi[(size_t)m0 * EMB], &g_a_lo[(size_t)m0 * EMB],
        &g_b_hi[(size_t)o0 * EMB]};

    auto issue = [&](int chunk) {
        const int kt = chunk * GBK;
        const uint32_t stage = sb + (chunk & 1) * STG_B;
#pragma unroll
        for (int t = 0; t < 3; t++) {
            const __half* gp = srcs[t] + kt;
            const uint32_t tb = stage + t * TILE_B;
#pragma unroll
            for (int i = 0; i < 2; i++) {
                int lin = tid + i * 256;          // 0..511
                int row = lin >> 2;
                int seg = lin & 3;
                cp_async16(tb + row * ROWB + seg * 16, gp + (size_t)row * EMB + seg * 8);
            }
        }
        cp_commit();
    };

    float acc[4][4][4];
#pragma unroll
    for (int i = 0; i < 4; i++)
#pragma unroll
        for (int j = 0; j < 4; j++)
#pragma unroll
            for (int c = 0; c < 4; c++) acc[i][j][c] = 0.f;

    issue(0);

    const uint32_t aRow0 = wm * 64 + g;
    const uint32_t bRow0 = wn * 32 + g;

    for (int chunk = 0; chunk < EMB / GBK; ++chunk) {
        if (chunk + 1 < EMB / GBK) { issue(chunk + 1); cp_wait1(); }
        else                       { cp_wait0(); }
        __syncthreads();

        const uint32_t stage = sb + (chunk & 1) * STG_B;

#pragma unroll
        for (int kk = 0; kk < 2; kk++) {
            const uint32_t klo = kk * 32 + tg * 4;

            uint32_t afr[4][4], bfr[4][2];
            // B hi fragments
#pragma unroll
            for (int nt = 0; nt < 4; nt++) {
                uint32_t base = stage + (bRow0 + nt * 8) * ROWB + klo + T_BHI;
                bfr[nt][0] = lds32(base);
                bfr[nt][1] = lds32(base + 16);
            }
            // pass 1: Ahi x Bhi
#pragma unroll
            for (int mt = 0; mt < 4; mt++) {
                uint32_t base = stage + (aRow0 + mt * 16) * ROWB + klo + T_AHI;
                afr[mt][0] = lds32(base);
                afr[mt][1] = lds32(base + 8 * ROWB);
                afr[mt][2] = lds32(base + 16);
                afr[mt][3] = lds32(base + 8 * ROWB + 16);
            }
#pragma unroll
            for (int mt = 0; mt < 4; mt++)
#pragma unroll
                for (int nt = 0; nt < 4; nt++)
                    mma_f16(acc[mt][nt][0], acc[mt][nt][1], acc[mt][nt][2], acc[mt][nt][3],
                            afr[mt][0], afr[mt][1], afr[mt][2], afr[mt][3],
                            bfr[nt][0], bfr[nt][1]);
            // pass 2: Alo x Bhi
#pragma unroll
            for (int mt = 0; mt < 4; mt++) {
                uint32_t base = stage + (aRow0 + mt * 16) * ROWB + klo + T_ALO;
                afr[mt][0] = lds32(base);
                afr[mt][1] = lds32(base + 8 * ROWB);
                afr[mt][2] = lds32(base + 16);
                afr[mt][3] = lds32(base + 8 * ROWB + 16);
            }
#pragma unroll
            for (int mt = 0; mt < 4; mt++)
#pragma unroll
                for (int nt = 0; nt < 4; nt++)
                    mma_f16(acc[mt][nt][0], acc[mt][nt][1], acc[mt][nt][2], acc[mt][nt][3],
                            afr[mt][0], afr[mt][1], afr[mt][2], afr[mt][3],
                            bfr[nt][0], bfr[nt][1]);
        }
        __syncthreads();
    }

    // epilogue: add bias, scatter to g_qkv [part][h][n][d]
    const float* sbias = reinterpret_cast<const float*>(smem + SM_BIAS);
#pragma unroll
    for (int mt = 0; mt < 4; mt++) {
        const int m = m0 + wm * 64 + mt * 16 + g;
#pragma unroll
        for (int nt = 0; nt < 4; nt++) {
            const int off = wn * 32 + nt * 8 + 2 * tg;
            const int o = o0 + off;
            const int part = o >> 9;
            const int h = (o >> 6) & 7;
            const int d = o & 63;
            const float bv0 = sbias[off], bv1 = sbias[off + 1];
            float* base = &g_qkv[(size_t)part * PSTRIDE + (size_t)h * HSTRIDE];
            float2 r0 = {acc[mt][nt][0] + bv0, acc[mt][nt][1] + bv1};
            float2 r1 = {acc[mt][nt][2] + bv0, acc[mt][nt][3] + bv1};
            *reinterpret_cast<float2*>(&base[(size_t)m * DH + d]) = r0;
            *reinterpret_cast<float2*>(&base[(size_t)(m + 8) * DH + d]) = r1;
        }
    }

    // fused qsum partial: q-part blocks (o0 < 512) reduce their 128-row colsums
    if (o0 < 512) {
        float* qs = reinterpret_cast<float*>(smem + SM_QS);   // [2][128]
        float cs[8];
#pragma unroll
        for (int nt = 0; nt < 4; nt++)
#pragma unroll
            for (int j = 0; j < 2; j++) {
                const int off = wn * 32 + nt * 8 + 2 * tg + j;
                float s = 8.f * sbias[off];
#pragma unroll
                for (int mt = 0; mt < 4; mt++)
                    s += acc[mt][nt][j] + acc[mt][nt][j + 2];
                cs[nt * 2 + j] = s;
            }
        // reduce over g (lanes differing in bits 2..4)
#pragma unroll
        for (int i = 0; i < 8; i++) {
#pragma unroll
            for (int off = 4; off < 32; off <<= 1)
                cs[i] += __shfl_xor_sync(0xffffffffu, cs[i], off);
        }
        if (g == 0) {
#pragma unroll
            for (int nt = 0; nt < 4; nt++)
#pragma unroll
                for (int j = 0; j < 2; j++)
                    qs[wm * 128 + wn * 32 + nt * 8 + 2 * tg + j] = cs[nt * 2 + j];
        }
        __syncthreads();
        if (tid < 128)
            g_qsum_part[blockIdx.y * 512 + o0 + tid] = qs[tid] + qs[128 + tid];
    }
}

// ---------------------------------------------------------------------------
// qsum final reduce (partials already include bias)
// ---------------------------------------------------------------------------
__global__ __launch_bounds__(512) void qsum_reduce_kernel() {
    int i = threadIdx.x;       // h*64+d
    float s = 0.f;
#pragma unroll
    for (int sp = 0; sp < 32; sp++) s += g_qsum_part[sp * (HEADS * 64) + i];
    g_qsum[i] = s;
}

// ---------------------------------------------------------------------------
// partial KtV over 32 N-splits (deterministic)
// ---------------------------------------------------------------------------
__global__ __launch_bounds__(256) void ktv_kernel() {
    int h = blockIdx.x;
    int split = blockIdx.y;
    const float* Kp = &g_qkv[(size_t)1 * PSTRIDE + (size_t)h * HSTRIDE];
    const float* Vp = &g_qkv[(size_t)2 * PSTRIDE + (size_t)h * HSTRIDE];

    __shared__ float sK[32][64];
    __shared__ float sV[32][64];

    int tid = threadIdx.x;
    int d1b = (tid >> 4) << 2;
    int d2b = (tid & 15) << 2;
    float acc[4][4];
#pragma unroll
    for (int i = 0; i < 4; i++)
#pragma unroll
        for (int j = 0; j < 4; j++) acc[i][j] = 0.f;

    int nbase = split * 128;
    for (int nc = 0; nc < 128; nc += 32) {
#pragma unroll
        for (int i = 0; i < 2; i++) {
            int lin = tid + i * 256;
            int r = lin >> 4;
            int c = (lin & 15) << 2;
            *reinterpret_cast<float4*>(&sK[r][c]) =
                *reinterpret_cast<const float4*>(&Kp[(size_t)(nbase + nc + r) * DH + c]);
            *reinterpret_cast<float4*>(&sV[r][c]) =
                *reinterpret_cast<const float4*>(&Vp[(size_t)(nbase + nc + r) * DH + c]);
        }
        __syncthreads();
#pragma unroll
        for (int nn = 0; nn < 32; nn++) {
            float4 rk = *reinterpret_cast<const float4*>(&sK[nn][d1b]);
            float4 rv = *reinterpret_cast<const float4*>(&sV[nn][d2b]);
            float k[4] = {rk.x, rk.y, rk.z, rk.w};
            float v[4] = {rv.x, rv.y, rv.z, rv.w};
#pragma unroll
            for (int i = 0; i < 4; i++)
#pragma unroll
                for (int j = 0; j < 4; j++) acc[i][j] += k[i] * v[j];
        }
        __syncthreads();
    }

    float* dst = &g_ktv_part[(size_t)split * (HEADS * DH * DH) + (size_t)h * DH * DH];
#pragma unroll
    for (int i = 0; i < 4; i++) {
        float4 v = {acc[i][0], acc[i][1], acc[i][2], acc[i][3]};
        *reinterpret_cast<float4*>(&dst[(d1b + i) * DH + d2b]) = v;
    }
}

__global__ void ktv_reduce() {
    int i = blockIdx.x * 256 + threadIdx.x;
    float s = 0.f;
#pragma unroll
    for (int sp = 0; sp < 32; sp++) s += g_ktv_part[(size_t)sp * (HEADS * DH * DH) + i];
    g_ktv[i] = s;
}

// ---------------------------------------------------------------------------
// out[h][n][:] = SCALE * q[n] @ KtV[h];  coarse[h][n] = SCALE * dot(k[n], qsum[h])
// ---------------------------------------------------------------------------
__global__ __launch_bounds__(128) void out_kernel(float* __restrict__ coarse,
                                                  float* __restrict__ out) {
    int h = blockIdx.x;
    int nt = blockIdx.y;
    int tid = threadIdx.x;
    int n = nt * 128 + tid;

    __shared__ float sM[DH * DH];
    __shared__ float sQs[DH];
#pragma unroll
    for (int i = 0; i < 8; i++) {
        int lin = tid + i * 128;
        *reinterpret_cast<float4*>(&sM[lin * 4]) =
            *reinterpret_cast<const float4*>(&g_ktv[(size_t)h * DH * DH + lin * 4]);
    }
    if (tid < 64) sQs[tid] = g_qsum[h * 64 + tid];
    __syncthreads();

    const float* Qr = &g_qkv[(size_t)h * HSTRIDE + (size_t)n * DH];
    const float* Kr = &g_qkv[(size_t)1 * PSTRIDE + (size_t)h * HSTRIDE + (size_t)n * DH];

    float qr[64];
    float cacc = 0.f;
#pragma unroll
    for (int d4 = 0; d4 < 64; d4 += 4) {
        float4 q4 = *reinterpret_cast<const float4*>(&Qr[d4]);
        qr[d4] = q4.x; qr[d4 + 1] = q4.y; qr[d4 + 2] = q4.z; qr[d4 + 3] = q4.w;
        float4 k4 = *reinterpret_cast<const float4*>(&Kr[d4]);
        cacc += k4.x * sQs[d4] + k4.y * sQs[d4 + 1] + k4.z * sQs[d4 + 2] + k4.w * sQs[d4 + 3];
    }
    coarse[h * TOK + n] = cacc * SCALE;

    float* op = &out[((size_t)h * TOK + n) * DH];
#pragma unroll
    for (int d2 = 0; d2 < 64; d2 += 4) {
        float a0 = 0.f, a1 = 0.f, a2 = 0.f, a3 = 0.f;
#pragma unroll
        for (int d1 = 0; d1 < 64; d1++) {
            float4 m4 = *reinterpret_cast<const float4*>(&sM[d1 * 64 + d2]);
            float q = qr[d1];
            a0 += q * m4.x; a1 += q * m4.y; a2 += q * m4.z; a3 += q * m4.w;
        }
        float4 v = {a0 * SCALE, a1 * SCALE, a2 * SCALE, a3 * SCALE};
        *reinterpret_cast<float4*>(&op[d2]) = v;
    }
}

// ---------------------------------------------------------------------------
extern "C" void kernel_launch(void* const* d_in, const int* in_sizes, int n_in,
                              void* d_out, int out_size) {
    const float* x = (const float*)d_in[0];   // [512, 4096]
    const float* W = (const float*)d_in[1];   // [512, 1536]
    const float* b = (const float*)d_in[2];   // [1536]

    float* coarse = (float*)d_out;
    float* out    = (float*)d_out + HEADS * TOK;

    __half *ahi, *alo, *bhi;
    cudaGetSymbolAddress((void**)&ahi, g_a_hi);
    cudaGetSymbolAddress((void**)&alo, g_a_lo);
    cudaGetSymbolAddress((void**)&bhi, g_b_hi);

    cudaFuncSetAttribute(qkv_gemm_mma, cudaFuncAttributeMaxDynamicSharedMemorySize, SM_TOT);

    splitA<<<dim3(TOK / 32, EMB / 32), 256>>>(x, ahi, alo);
    convB<<<dim3(QKVN / 32, EMB / 32), 256>>>(W, bhi);

    qkv_gemm_mma<<<dim3(QKVN / GBN, TOK / GBM), 256, SM_TOT>>>(b);

    qsum_reduce_kernel<<<1, 512>>>();
    ktv_kernel<<<dim3(HEADS, 32), 256>>>();
    ktv_reduce<<<128, 256>>>();
    out_kernel<<<dim3(HEADS, 32), 128>>>(coarse, out);
}

// round 6
// speedup vs baseline: 3.0963x; 1.2956x over previous
#include <cuda_runtime.h>
#include <cuda_fp16.h>
#include <cstdint>

#define TOK   4096
#define EMB   512
#define QKVN  1536
#define HEADS 8
#define DH    64
#define SCALE 0.125f

#define HSTRIDE (TOK * DH)           // 262144
#define PSTRIDE (HEADS * TOK * DH)   // 2097152

// ---------------- scratch (device globals) ----------------
__device__ float g_qkv[3 * HEADS * TOK * DH];        // [part][h][n][d]
__device__ float g_qsum[HEADS * DH];
__device__ float g_qsum_part[32 * HEADS * DH];       // [m_block][h*64+d]
__device__ float g_ktv[HEADS * DH * DH];
__device__ float g_ktv_part[32 * HEADS * DH * DH];

__device__ __half g_a_hi[TOK * EMB];                 // A = x^T  [4096, 512]
__device__ __half g_b_hi[QKVN * EMB];                // B = W^T  [1536, 512]

// ---------------- helpers ----------------
__device__ __forceinline__ uint32_t smem_u32(const void* p) {
    uint32_t a;
    asm("{ .reg .u64 t; cvta.to.shared.u64 t, %1; cvt.u32.u64 %0, t; }" : "=r"(a) : "l"(p));
    return a;
}
__device__ __forceinline__ uint32_t lds32(uint32_t a) {
    uint32_t v;
    asm volatile("ld.shared.b32 %0, [%1];" : "=r"(v) : "r"(a));
    return v;
}
__device__ __forceinline__ void cp_async16(uint32_t saddr, const void* gaddr) {
    asm volatile("cp.async.cg.shared.global [%0], [%1], 16;" :: "r"(saddr), "l"(gaddr));
}
__device__ __forceinline__ void cp_commit() { asm volatile("cp.async.commit_group;"); }
__device__ __forceinline__ void cp_wait1()  { asm volatile("cp.async.wait_group 1;"); }
__device__ __forceinline__ void cp_wait0()  { asm volatile("cp.async.wait_group 0;"); }

__device__ __forceinline__ void mma_f16(float& c0, float& c1, float& c2, float& c3,
                                        uint32_t a0, uint32_t a1, uint32_t a2, uint32_t a3,
                                        uint32_t b0, uint32_t b1) {
    asm volatile(
        "mma.sync.aligned.m16n8k16.row.col.f32.f16.f16.f32 "
        "{%0,%1,%2,%3}, {%4,%5,%6,%7}, {%8,%9}, {%0,%1,%2,%3};"
        : "+f"(c0), "+f"(c1), "+f"(c2), "+f"(c3)
        : "r"(a0), "r"(a1), "r"(a2), "r"(a3), "r"(b0), "r"(b1));
}

// ---------------------------------------------------------------------------
// Pre-pass: transpose src[512, Mcols] f32 -> dhi [Mcols, 512] fp16
// ---------------------------------------------------------------------------
__global__ __launch_bounds__(256) void conv_transpose(const float* __restrict__ src,
                                                      __half* __restrict__ dhi,
                                                      int Mcols) {
    __shared__ float tile[32][33];
    int tx = threadIdx.x & 31, ty = threadIdx.x >> 5;
    int m0 = blockIdx.x * 32, k0 = blockIdx.y * 32;
#pragma unroll
    for (int j = 0; j < 4; j++)
        tile[ty + j * 8][tx] = src[(size_t)(k0 + ty + j * 8) * Mcols + m0 + tx];
    __syncthreads();
#pragma unroll
    for (int j = 0; j < 4; j++) {
        int m = m0 + ty + j * 8;
        dhi[(size_t)m * EMB + k0 + tx] = __float2half_rn(tile[tx][ty + j * 8]);
    }
}

// ---------------------------------------------------------------------------
// mma.sync QKV GEMM: D[m, o] = sum_k A[m,k]*B[o,k] + bias[o]
// block 128x128, BK=32, single-pass fp16, fp32 accum, occ 2.
// q-part blocks also emit per-block column sums -> g_qsum_part.
// ---------------------------------------------------------------------------
#define GBM 128
#define GBN 128
#define GBK 32
#define ROWB   80                  // bytes per smem row (32 halves + pad)
#define TILE_B (128 * ROWB)        // 10240
#define T_AHI  0
#define T_BHI  (1 * TILE_B)
#define STG_B  (2 * TILE_B)        // 20480
#define SM_BIAS (2 * STG_B)        // 40960
#define SM_QS   (SM_BIAS + 512)    // 41472 (2*128 floats)
#define SM_TOT  (SM_QS + 1024)

__global__ void __launch_bounds__(256, 2) qkv_gemm_mma(const float* __restrict__ bias) {
    extern __shared__ char smem[];
    const uint32_t sb = smem_u32(smem);
    const int tid  = threadIdx.x;
    const int wid  = tid >> 5;
    const int lane = tid & 31;
    const int g    = lane >> 2;
    const int tg   = lane & 3;
    const int wm   = wid >> 2;         // 0..1
    const int wn   = wid & 3;          // 0..3
    const int o0   = blockIdx.x * GBN;
    const int m0   = blockIdx.y * GBM;

    if (tid < 128) *reinterpret_cast<float*>(smem + SM_BIAS + tid * 4) = bias[o0 + tid];

    const __half* srcs[2] = {
        &g_a_hi[(size_t)m0 * EMB], &g_b_hi[(size_t)o0 * EMB]};

    auto issue = [&](int chunk) {
        const int kt = chunk * GBK;
        const uint32_t stage = sb + (chunk & 1) * STG_B;
#pragma unroll
        for (int t = 0; t < 2; t++) {
            const __half* gp = srcs[t] + kt;
            const uint32_t tb = stage + t * TILE_B;
#pragma unroll
            for (int i = 0; i < 2; i++) {
                int lin = tid + i * 256;          // 0..511
                int row = lin >> 2;
                int seg = lin & 3;
                cp_async16(tb + row * ROWB + seg * 16, gp + (size_t)row * EMB + seg * 8);
            }
        }
        cp_commit();
    };

    float acc[4][4][4];
#pragma unroll
    for (int i = 0; i < 4; i++)
#pragma unroll
        for (int j = 0; j < 4; j++)
#pragma unroll
            for (int c = 0; c < 4; c++) acc[i][j][c] = 0.f;

    issue(0);

    const uint32_t aRow0 = wm * 64 + g;
    const uint32_t bRow0 = wn * 32 + g;

    for (int chunk = 0; chunk < EMB / GBK; ++chunk) {
        if (chunk + 1 < EMB / GBK) { issue(chunk + 1); cp_wait1(); }
        else                       { cp_wait0(); }
        __syncthreads();

        const uint32_t stage = sb + (chunk & 1) * STG_B;

#pragma unroll
        for (int kk = 0; kk < 2; kk++) {
            const uint32_t klo = kk * 32 + tg * 4;

            uint32_t afr[4][4], bfr[4][2];
#pragma unroll
            for (int nt = 0; nt < 4; nt++) {
                uint32_t base = stage + (bRow0 + nt * 8) * ROWB + klo + T_BHI;
                bfr[nt][0] = lds32(base);
                bfr[nt][1] = lds32(base + 16);
            }
#pragma unroll
            for (int mt = 0; mt < 4; mt++) {
                uint32_t base = stage + (aRow0 + mt * 16) * ROWB + klo + T_AHI;
                afr[mt][0] = lds32(base);
                afr[mt][1] = lds32(base + 8 * ROWB);
                afr[mt][2] = lds32(base + 16);
                afr[mt][3] = lds32(base + 8 * ROWB + 16);
            }
#pragma unroll
            for (int mt = 0; mt < 4; mt++)
#pragma unroll
                for (int nt = 0; nt < 4; nt++)
                    mma_f16(acc[mt][nt][0], acc[mt][nt][1], acc[mt][nt][2], acc[mt][nt][3],
                            afr[mt][0], afr[mt][1], afr[mt][2], afr[mt][3],
                            bfr[nt][0], bfr[nt][1]);
        }
        __syncthreads();
    }

    // epilogue: add bias, scatter to g_qkv [part][h][n][d]
    const float* sbias = reinterpret_cast<const float*>(smem + SM_BIAS);
#pragma unroll
    for (int mt = 0; mt < 4; mt++) {
        const int m = m0 + wm * 64 + mt * 16 + g;
#pragma unroll
        for (int nt = 0; nt < 4; nt++) {
            const int off = wn * 32 + nt * 8 + 2 * tg;
            const int o = o0 + off;
            const int part = o >> 9;
            const int h = (o >> 6) & 7;
            const int d = o & 63;
            const float bv0 = sbias[off], bv1 = sbias[off + 1];
            float* base = &g_qkv[(size_t)part * PSTRIDE + (size_t)h * HSTRIDE];
            float2 r0 = {acc[mt][nt][0] + bv0, acc[mt][nt][1] + bv1};
            float2 r1 = {acc[mt][nt][2] + bv0, acc[mt][nt][3] + bv1};
            *reinterpret_cast<float2*>(&base[(size_t)m * DH + d]) = r0;
            *reinterpret_cast<float2*>(&base[(size_t)(m + 8) * DH + d]) = r1;
        }
    }

    // fused qsum partial: q-part blocks (o0 < 512) reduce their 128-row colsums
    if (o0 < 512) {
        float* qs = reinterpret_cast<float*>(smem + SM_QS);   // [2][128]
        float cs[8];
#pragma unroll
        for (int nt = 0; nt < 4; nt++)
#pragma unroll
            for (int j = 0; j < 2; j++) {
                const int off = wn * 32 + nt * 8 + 2 * tg + j;
                float s = 8.f * sbias[off];
#pragma unroll
                for (int mt = 0; mt < 4; mt++)
                    s += acc[mt][nt][j] + acc[mt][nt][j + 2];
                cs[nt * 2 + j] = s;
            }
#pragma unroll
        for (int i = 0; i < 8; i++) {
#pragma unroll
            for (int off = 4; off < 32; off <<= 1)
                cs[i] += __shfl_xor_sync(0xffffffffu, cs[i], off);
        }
        if (g == 0) {
#pragma unroll
            for (int nt = 0; nt < 4; nt++)
#pragma unroll
                for (int j = 0; j < 2; j++)
                    qs[wm * 128 + wn * 32 + nt * 8 + 2 * tg + j] = cs[nt * 2 + j];
        }
        __syncthreads();
        if (tid < 128)
            g_qsum_part[blockIdx.y * 512 + o0 + tid] = qs[tid] + qs[128 + tid];
    }
}

// ---------------------------------------------------------------------------
// partial KtV over 32 N-splits (deterministic)
// ---------------------------------------------------------------------------
__global__ __launch_bounds__(256) void ktv_kernel() {
    int h = blockIdx.x;
    int split = blockIdx.y;
    const float* Kp = &g_qkv[(size_t)1 * PSTRIDE + (size_t)h * HSTRIDE];
    const float* Vp = &g_qkv[(size_t)2 * PSTRIDE + (size_t)h * HSTRIDE];

    __shared__ float sK[32][64];
    __shared__ float sV[32][64];

    int tid = threadIdx.x;
    int d1b = (tid >> 4) << 2;
    int d2b = (tid & 15) << 2;
    float acc[4][4];
#pragma unroll
    for (int i = 0; i < 4; i++)
#pragma unroll
        for (int j = 0; j < 4; j++) acc[i][j] = 0.f;

    int nbase = split * 128;
    for (int nc = 0; nc < 128; nc += 32) {
#pragma unroll
        for (int i = 0; i < 2; i++) {
            int lin = tid + i * 256;
            int r = lin >> 4;
            int c = (lin & 15) << 2;
            *reinterpret_cast<float4*>(&sK[r][c]) =
                *reinterpret_cast<const float4*>(&Kp[(size_t)(nbase + nc + r) * DH + c]);
            *reinterpret_cast<float4*>(&sV[r][c]) =
                *reinterpret_cast<const float4*>(&Vp[(size_t)(nbase + nc + r) * DH + c]);
        }
        __syncthreads();
#pragma unroll
        for (int nn = 0; nn < 32; nn++) {
            float4 rk = *reinterpret_cast<const float4*>(&sK[nn][d1b]);
            float4 rv = *reinterpret_cast<const float4*>(&sV[nn][d2b]);
            float k[4] = {rk.x, rk.y, rk.z, rk.w};
            float v[4] = {rv.x, rv.y, rv.z, rv.w};
#pragma unroll
            for (int i = 0; i < 4; i++)
#pragma unroll
                for (int j = 0; j < 4; j++) acc[i][j] += k[i] * v[j];
        }
        __syncthreads();
    }

    float* dst = &g_ktv_part[(size_t)split * (HEADS * DH * DH) + (size_t)h * DH * DH];
#pragma unroll
    for (int i = 0; i < 4; i++) {
        float4 v = {acc[i][0], acc[i][1], acc[i][2], acc[i][3]};
        *reinterpret_cast<float4*>(&dst[(d1b + i) * DH + d2b]) = v;
    }
}

// ktv reduce + fused qsum reduce (blocks 0-1 handle qsum's 512 entries)
__global__ void ktv_reduce() {
    int i = blockIdx.x * 256 + threadIdx.x;
    float s = 0.f;
#pragma unroll
    for (int sp = 0; sp < 32; sp++) s += g_ktv_part[(size_t)sp * (HEADS * DH * DH) + i];
    g_ktv[i] = s;
    if (i < HEADS * DH) {
        float q = 0.f;
#pragma unroll
        for (int sp = 0; sp < 32; sp++) q += g_qsum_part[sp * (HEADS * DH) + i];
        g_qsum[i] = q;
    }
}

// ---------------------------------------------------------------------------
// out[h][n][:] = SCALE * q[n] @ KtV[h];  coarse[h][n] = SCALE * dot(k[n], qsum[h])
// ---------------------------------------------------------------------------
__global__ __launch_bounds__(128) void out_kernel(float* __restrict__ coarse,
                                                  float* __restrict__ out) {
    int h = blockIdx.x;
    int nt = blockIdx.y;
    int tid = threadIdx.x;
    int n = nt * 128 + tid;

    __shared__ float sM[DH * DH];
    __shared__ float sQs[DH];
#pragma unroll
    for (int i = 0; i < 8; i++) {
        int lin = tid + i * 128;
        *reinterpret_cast<float4*>(&sM[lin * 4]) =
            *reinterpret_cast<const float4*>(&g_ktv[(size_t)h * DH * DH + lin * 4]);
    }
    if (tid < 64) sQs[tid] = g_qsum[h * 64 + tid];
    __syncthreads();

    const float* Qr = &g_qkv[(size_t)h * HSTRIDE + (size_t)n * DH];
    const float* Kr = &g_qkv[(size_t)1 * PSTRIDE + (size_t)h * HSTRIDE + (size_t)n * DH];

    float qr[64];
    float cacc = 0.f;
#pragma unroll
    for (int d4 = 0; d4 < 64; d4 += 4) {
        float4 q4 = *reinterpret_cast<const float4*>(&Qr[d4]);
        qr[d4] = q4.x; qr[d4 + 1] = q4.y; qr[d4 + 2] = q4.z; qr[d4 + 3] = q4.w;
        float4 k4 = *reinterpret_cast<const float4*>(&Kr[d4]);
        cacc += k4.x * sQs[d4] + k4.y * sQs[d4 + 1] + k4.z * sQs[d4 + 2] + k4.w * sQs[d4 + 3];
    }
    coarse[h * TOK + n] = cacc * SCALE;

    float* op = &out[((size_t)h * TOK + n) * DH];
#pragma unroll
    for (int d2 = 0; d2 < 64; d2 += 4) {
        float a0 = 0.f, a1 = 0.f, a2 = 0.f, a3 = 0.f;
#pragma unroll
        for (int d1 = 0; d1 < 64; d1++) {
            float4 m4 = *reinterpret_cast<const float4*>(&sM[d1 * 64 + d2]);
            float q = qr[d1];
            a0 += q * m4.x; a1 += q * m4.y; a2 += q * m4.z; a3 += q * m4.w;
        }
        float4 v = {a0 * SCALE, a1 * SCALE, a2 * SCALE, a3 * SCALE};
        *reinterpret_cast<float4*>(&op[d2]) = v;
    }
}

// ---------------------------------------------------------------------------
extern "C" void kernel_launch(void* const* d_in, const int* in_sizes, int n_in,
                              void* d_out, int out_size) {
    const float* x = (const float*)d_in[0];   // [512, 4096]
    const float* W = (const float*)d_in[1];   // [512, 1536]
    const float* b = (const float*)d_in[2];   // [1536]

    float* coarse = (float*)d_out;
    float* out    = (float*)d_out + HEADS * TOK;

    __half *ahi, *bhi;
    cudaGetSymbolAddress((void**)&ahi, g_a_hi);
    cudaGetSymbolAddress((void**)&bhi, g_b_hi);

    cudaFuncSetAttribute(qkv_gemm_mma, cudaFuncAttributeMaxDynamicSharedMemorySize, SM_TOT);

    conv_transpose<<<dim3(TOK / 32, EMB / 32), 256>>>(x, ahi, TOK);
    conv_transpose<<<dim3(QKVN / 32, EMB / 32), 256>>>(W, bhi, QKVN);

    qkv_gemm_mma<<<dim3(QKVN / GBN, TOK / GBM), 256, SM_TOT>>>(b);

    ktv_kernel<<<dim3(HEADS, 32), 256>>>();
    ktv_reduce<<<128, 256>>>();
    out_kernel<<<dim3(HEADS, 32), 128>>>(coarse, out);
}

// round 7
// speedup vs baseline: 3.1894x; 1.0301x over previous
#include <cuda_runtime.h>
#include <cuda_fp16.h>
#include <cstdint>

#define TOK   4096
#define EMB   512
#define QKVN  1536
#define HEADS 8
#define DH    64
#define SCALE 0.125f

#define HSTRIDE (TOK * DH)           // 262144
#define PSTRIDE (HEADS * TOK * DH)   // 2097152

// ---------------- scratch (device globals) ----------------
__device__ float g_qkv[3 * HEADS * TOK * DH];        // [part][h][n][d]
__device__ float g_qsum[HEADS * DH];
__device__ float g_qsum_part[32 * HEADS * DH];       // [m_block][h*64+d]
__device__ float g_ktv[HEADS * DH * DH];
__device__ float g_ktv_part[32 * HEADS * DH * DH];

__device__ __half g_a_hi[TOK * EMB];                 // A = x^T  [4096, 512]
__device__ __half g_b_hi[QKVN * EMB];                // B = W^T  [1536, 512]

// ---------------- helpers ----------------
__device__ __forceinline__ uint32_t smem_u32(const void* p) {
    uint32_t a;
    asm("{ .reg .u64 t; cvta.to.shared.u64 t, %1; cvt.u32.u64 %0, t; }" : "=r"(a) : "l"(p));
    return a;
}
__device__ __forceinline__ uint32_t lds32(uint32_t a) {
    uint32_t v;
    asm volatile("ld.shared.b32 %0, [%1];" : "=r"(v) : "r"(a));
    return v;
}
__device__ __forceinline__ void cp_async16(uint32_t saddr, const void* gaddr) {
    asm volatile("cp.async.cg.shared.global [%0], [%1], 16;" :: "r"(saddr), "l"(gaddr));
}
__device__ __forceinline__ void cp_commit() { asm volatile("cp.async.commit_group;"); }
__device__ __forceinline__ void cp_wait1()  { asm volatile("cp.async.wait_group 1;"); }
__device__ __forceinline__ void cp_wait0()  { asm volatile("cp.async.wait_group 0;"); }

__device__ __forceinline__ void mma_f16(float& c0, float& c1, float& c2, float& c3,
                                        uint32_t a0, uint32_t a1, uint32_t a2, uint32_t a3,
                                        uint32_t b0, uint32_t b1) {
    asm volatile(
        "mma.sync.aligned.m16n8k16.row.col.f32.f16.f16.f32 "
        "{%0,%1,%2,%3}, {%4,%5,%6,%7}, {%8,%9}, {%0,%1,%2,%3};"
        : "+f"(c0), "+f"(c1), "+f"(c2), "+f"(c3)
        : "r"(a0), "r"(a1), "r"(a2), "r"(a3), "r"(b0), "r"(b1));
}

// packed fp32x2 (Blackwell FFMA2 path, exact fp32 semantics)
__device__ __forceinline__ unsigned long long dup2(float x) {
    unsigned long long r;
    asm("mov.b64 %0, {%1, %1};" : "=l"(r) : "f"(x));
    return r;
}
__device__ __forceinline__ unsigned long long fma2(unsigned long long a,
                                                   unsigned long long b,
                                                   unsigned long long c) {
    unsigned long long d;
    asm("fma.rn.f32x2 %0, %1, %2, %3;" : "=l"(d) : "l"(a), "l"(b), "l"(c));
    return d;
}
__device__ __forceinline__ void unpack2(unsigned long long v, float& x, float& y) {
    asm("mov.b64 {%0, %1}, %2;" : "=f"(x), "=f"(y) : "l"(v));
}
__device__ __forceinline__ void lds_v2u64(uint32_t addr, unsigned long long& a,
                                          unsigned long long& b) {
    asm volatile("ld.shared.v2.u64 {%0, %1}, [%2];" : "=l"(a), "=l"(b) : "r"(addr));
}

// ---------------------------------------------------------------------------
// Pre-pass: transpose src[512, Mcols] f32 -> dhi [Mcols, 512] fp16
// ---------------------------------------------------------------------------
__global__ __launch_bounds__(256) void conv_transpose(const float* __restrict__ src,
                                                      __half* __restrict__ dhi,
                                                      int Mcols) {
    __shared__ float tile[32][33];
    int tx = threadIdx.x & 31, ty = threadIdx.x >> 5;
    int m0 = blockIdx.x * 32, k0 = blockIdx.y * 32;
#pragma unroll
    for (int j = 0; j < 4; j++)
        tile[ty + j * 8][tx] = src[(size_t)(k0 + ty + j * 8) * Mcols + m0 + tx];
    __syncthreads();
#pragma unroll
    for (int j = 0; j < 4; j++) {
        int m = m0 + ty + j * 8;
        dhi[(size_t)m * EMB + k0 + tx] = __float2half_rn(tile[tx][ty + j * 8]);
    }
}

// ---------------------------------------------------------------------------
// mma.sync QKV GEMM: D[m, o] = sum_k A[m,k]*B[o,k] + bias[o]
// block 128x128, BK=32, single-pass fp16, fp32 accum, occ 2.
// q-part blocks also emit per-block column sums -> g_qsum_part.
// ---------------------------------------------------------------------------
#define GBM 128
#define GBN 128
#define GBK 32
#define ROWB   80
#define TILE_B (128 * ROWB)
#define T_AHI  0
#define T_BHI  (1 * TILE_B)
#define STG_B  (2 * TILE_B)
#define SM_BIAS (2 * STG_B)
#define SM_QS   (SM_BIAS + 512)
#define SM_TOT  (SM_QS + 1024)

__global__ void __launch_bounds__(256, 2) qkv_gemm_mma(const float* __restrict__ bias) {
    extern __shared__ char smem[];
    const uint32_t sb = smem_u32(smem);
    const int tid  = threadIdx.x;
    const int wid  = tid >> 5;
    const int lane = tid & 31;
    const int g    = lane >> 2;
    const int tg   = lane & 3;
    const int wm   = wid >> 2;
    const int wn   = wid & 3;
    const int o0   = blockIdx.x * GBN;
    const int m0   = blockIdx.y * GBM;

    if (tid < 128) *reinterpret_cast<float*>(smem + SM_BIAS + tid * 4) = bias[o0 + tid];

    const __half* srcs[2] = {
        &g_a_hi[(size_t)m0 * EMB], &g_b_hi[(size_t)o0 * EMB]};

    auto issue = [&](int chunk) {
        const int kt = chunk * GBK;
        const uint32_t stage = sb + (chunk & 1) * STG_B;
#pragma unroll
        for (int t = 0; t < 2; t++) {
            const __half* gp = srcs[t] + kt;
            const uint32_t tb = stage + t * TILE_B;
#pragma unroll
            for (int i = 0; i < 2; i++) {
                int lin = tid + i * 256;
                int row = lin >> 2;
                int seg = lin & 3;
                cp_async16(tb + row * ROWB + seg * 16, gp + (size_t)row * EMB + seg * 8);
            }
        }
        cp_commit();
    };

    float acc[4][4][4];
#pragma unroll
    for (int i = 0; i < 4; i++)
#pragma unroll
        for (int j = 0; j < 4; j++)
#pragma unroll
            for (int c = 0; c < 4; c++) acc[i][j][c] = 0.f;

    issue(0);

    const uint32_t aRow0 = wm * 64 + g;
    const uint32_t bRow0 = wn * 32 + g;

    for (int chunk = 0; chunk < EMB / GBK; ++chunk) {
        if (chunk + 1 < EMB / GBK) { issue(chunk + 1); cp_wait1(); }
        else                       { cp_wait0(); }
        __syncthreads();

        const uint32_t stage = sb + (chunk & 1) * STG_B;

#pragma unroll
        for (int kk = 0; kk < 2; kk++) {
            const uint32_t klo = kk * 32 + tg * 4;

            uint32_t afr[4][4], bfr[4][2];
#pragma unroll
            for (int nt = 0; nt < 4; nt++) {
                uint32_t base = stage + (bRow0 + nt * 8) * ROWB + klo + T_BHI;
                bfr[nt][0] = lds32(base);
                bfr[nt][1] = lds32(base + 16);
            }
#pragma unroll
            for (int mt = 0; mt < 4; mt++) {
                uint32_t base = stage + (aRow0 + mt * 16) * ROWB + klo + T_AHI;
                afr[mt][0] = lds32(base);
                afr[mt][1] = lds32(base + 8 * ROWB);
                afr[mt][2] = lds32(base + 16);
                afr[mt][3] = lds32(base + 8 * ROWB + 16);
            }
#pragma unroll
            for (int mt = 0; mt < 4; mt++)
#pragma unroll
                for (int nt = 0; nt < 4; nt++)
                    mma_f16(acc[mt][nt][0], acc[mt][nt][1], acc[mt][nt][2], acc[mt][nt][3],
                            afr[mt][0], afr[mt][1], afr[mt][2], afr[mt][3],
                            bfr[nt][0], bfr[nt][1]);
        }
        __syncthreads();
    }

    // epilogue: add bias, scatter to g_qkv [part][h][n][d]
    const float* sbias = reinterpret_cast<const float*>(smem + SM_BIAS);
#pragma unroll
    for (int mt = 0; mt < 4; mt++) {
        const int m = m0 + wm * 64 + mt * 16 + g;
#pragma unroll
        for (int nt = 0; nt < 4; nt++) {
            const int off = wn * 32 + nt * 8 + 2 * tg;
            const int o = o0 + off;
            const int part = o >> 9;
            const int h = (o >> 6) & 7;
            const int d = o & 63;
            const float bv0 = sbias[off], bv1 = sbias[off + 1];
            float* base = &g_qkv[(size_t)part * PSTRIDE + (size_t)h * HSTRIDE];
            float2 r0 = {acc[mt][nt][0] + bv0, acc[mt][nt][1] + bv1};
            float2 r1 = {acc[mt][nt][2] + bv0, acc[mt][nt][3] + bv1};
            *reinterpret_cast<float2*>(&base[(size_t)m * DH + d]) = r0;
            *reinterpret_cast<float2*>(&base[(size_t)(m + 8) * DH + d]) = r1;
        }
    }

    // fused qsum partial
    if (o0 < 512) {
        float* qs = reinterpret_cast<float*>(smem + SM_QS);
        float cs[8];
#pragma unroll
        for (int nt = 0; nt < 4; nt++)
#pragma unroll
            for (int j = 0; j < 2; j++) {
                const int off = wn * 32 + nt * 8 + 2 * tg + j;
                float s = 8.f * sbias[off];
#pragma unroll
                for (int mt = 0; mt < 4; mt++)
                    s += acc[mt][nt][j] + acc[mt][nt][j + 2];
                cs[nt * 2 + j] = s;
            }
#pragma unroll
        for (int i = 0; i < 8; i++) {
#pragma unroll
            for (int off = 4; off < 32; off <<= 1)
                cs[i] += __shfl_xor_sync(0xffffffffu, cs[i], off);
        }
        if (g == 0) {
#pragma unroll
            for (int nt = 0; nt < 4; nt++)
#pragma unroll
                for (int j = 0; j < 2; j++)
                    qs[wm * 128 + wn * 32 + nt * 8 + 2 * tg + j] = cs[nt * 2 + j];
        }
        __syncthreads();
        if (tid < 128)
            g_qsum_part[blockIdx.y * 512 + o0 + tid] = qs[tid] + qs[128 + tid];
    }
}

// ---------------------------------------------------------------------------
// partial KtV over 32 N-splits, f32x2, 8x4 acc per thread, 128 threads
// ---------------------------------------------------------------------------
__global__ __launch_bounds__(128) void ktv_kernel() {
    int h = blockIdx.x;
    int split = blockIdx.y;
    const float* Kp = &g_qkv[(size_t)1 * PSTRIDE + (size_t)h * HSTRIDE];
    const float* Vp = &g_qkv[(size_t)2 * PSTRIDE + (size_t)h * HSTRIDE];

    __shared__ float sK[32][64];
    __shared__ float sV[32][64];
    const uint32_t sKb = smem_u32(sK);
    const uint32_t sVb = smem_u32(sV);

    int tid = threadIdx.x;
    int d1b = (tid >> 4) * 8;          // 0..56 step 8
    int d2b = (tid & 15) * 4;          // 0..60 step 4

    unsigned long long acc2[8][2];
#pragma unroll
    for (int i = 0; i < 8; i++) { acc2[i][0] = 0ull; acc2[i][1] = 0ull; }

    int nbase = split * 128;
    for (int nc = 0; nc < 128; nc += 32) {
#pragma unroll
        for (int i = 0; i < 4; i++) {
            int lin = tid + i * 128;       // 0..511
            int r = lin >> 4;
            int c = (lin & 15) << 2;
            *reinterpret_cast<float4*>(&sK[r][c]) =
                *reinterpret_cast<const float4*>(&Kp[(size_t)(nbase + nc + r) * DH + c]);
            *reinterpret_cast<float4*>(&sV[r][c]) =
                *reinterpret_cast<const float4*>(&Vp[(size_t)(nbase + nc + r) * DH + c]);
        }
        __syncthreads();
#pragma unroll
        for (int nn = 0; nn < 32; nn++) {
            float4 k0 = *reinterpret_cast<const float4*>(&sK[nn][d1b]);
            float4 k1 = *reinterpret_cast<const float4*>(&sK[nn][d1b + 4]);
            unsigned long long v01, v23;
            lds_v2u64(sVb + (nn * 64 + d2b) * 4, v01, v23);
            unsigned long long kd;
            kd = dup2(k0.x); acc2[0][0] = fma2(kd, v01, acc2[0][0]); acc2[0][1] = fma2(kd, v23, acc2[0][1]);
            kd = dup2(k0.y); acc2[1][0] = fma2(kd, v01, acc2[1][0]); acc2[1][1] = fma2(kd, v23, acc2[1][1]);
            kd = dup2(k0.z); acc2[2][0] = fma2(kd, v01, acc2[2][0]); acc2[2][1] = fma2(kd, v23, acc2[2][1]);
            kd = dup2(k0.w); acc2[3][0] = fma2(kd, v01, acc2[3][0]); acc2[3][1] = fma2(kd, v23, acc2[3][1]);
            kd = dup2(k1.x); acc2[4][0] = fma2(kd, v01, acc2[4][0]); acc2[4][1] = fma2(kd, v23, acc2[4][1]);
            kd = dup2(k1.y); acc2[5][0] = fma2(kd, v01, acc2[5][0]); acc2[5][1] = fma2(kd, v23, acc2[5][1]);
            kd = dup2(k1.z); acc2[6][0] = fma2(kd, v01, acc2[6][0]); acc2[6][1] = fma2(kd, v23, acc2[6][1]);
            kd = dup2(k1.w); acc2[7][0] = fma2(kd, v01, acc2[7][0]); acc2[7][1] = fma2(kd, v23, acc2[7][1]);
        }
        __syncthreads();
    }

    float* dst = &g_ktv_part[(size_t)split * (HEADS * DH * DH) + (size_t)h * DH * DH];
#pragma unroll
    for (int i = 0; i < 8; i++) {
        float4 v;
        unpack2(acc2[i][0], v.x, v.y);
        unpack2(acc2[i][1], v.z, v.w);
        *reinterpret_cast<float4*>(&dst[(d1b + i) * DH + d2b]) = v;
    }
}

// ktv reduce + fused qsum reduce (first 512 lanes handle qsum)
__global__ void ktv_reduce() {
    int i = blockIdx.x * 256 + threadIdx.x;
    float s = 0.f;
#pragma unroll
    for (int sp = 0; sp < 32; sp++) s += g_ktv_part[(size_t)sp * (HEADS * DH * DH) + i];
    g_ktv[i] = s;
    if (i < HEADS * DH) {
        float q = 0.f;
#pragma unroll
        for (int sp = 0; sp < 32; sp++) q += g_qsum_part[sp * (HEADS * DH) + i];
        g_qsum[i] = q;
    }
}

// ---------------------------------------------------------------------------
// out[h][n][:] = SCALE * q[n] @ KtV[h];  coarse[h][n] = SCALE * dot(k[n], qsum[h])
// f32x2 accumulation, Q staged in smem (pad-65 rows), M via v2.u64 broadcast.
// ---------------------------------------------------------------------------
#define OQ_PAD 65
#define OSM_M   0                          // 64*64 floats = 16384 B
#define OSM_Q   16384                      // 128*65 floats = 33280 B
#define OSM_QS  (OSM_Q + 128 * OQ_PAD * 4) // 49664
#define OSM_TOT (OSM_QS + 256)             // 49920

__global__ void __launch_bounds__(128, 1) out_kernel(float* __restrict__ coarse,
                                                     float* __restrict__ out) {
    extern __shared__ char osm[];
    float* sM  = reinterpret_cast<float*>(osm + OSM_M);
    float* sQ  = reinterpret_cast<float*>(osm + OSM_Q);
    float* sQs = reinterpret_cast<float*>(osm + OSM_QS);
    const uint32_t sMb = smem_u32(sM);
    const uint32_t sQb = smem_u32(sQ);

    int h = blockIdx.x;
    int nt = blockIdx.y;
    int tid = threadIdx.x;
    int n = nt * 128 + tid;

    // stage M (broadcast source): 1024 float4 / 128 thr
#pragma unroll
    for (int i = 0; i < 8; i++) {
        int lin = tid + i * 128;
        *reinterpret_cast<float4*>(&sM[lin * 4]) =
            *reinterpret_cast<const float4*>(&g_ktv[(size_t)h * DH * DH + lin * 4]);
    }
    if (tid < 64) sQs[tid] = g_qsum[h * 64 + tid];

    // stage Q tile [128 rows][64], rows padded to 65 (scalar scatter)
    const float* Qg = &g_qkv[(size_t)h * HSTRIDE + (size_t)nt * 128 * DH];
#pragma unroll
    for (int i = 0; i < 16; i++) {
        int lin = tid + i * 128;           // 0..2047 float4s
        int r = lin >> 4;
        int c = (lin & 15) * 4;
        float4 v = *reinterpret_cast<const float4*>(&Qg[(size_t)r * DH + c]);
        float* dq = &sQ[r * OQ_PAD + c];
        dq[0] = v.x; dq[1] = v.y; dq[2] = v.z; dq[3] = v.w;
    }
    __syncthreads();

    // coarse: dot(k row, qsum)
    const float* Kr = &g_qkv[(size_t)1 * PSTRIDE + (size_t)h * HSTRIDE + (size_t)n * DH];
    float cacc = 0.f;
#pragma unroll
    for (int d4 = 0; d4 < 64; d4 += 4) {
        float4 k4 = *reinterpret_cast<const float4*>(&Kr[d4]);
        cacc += k4.x * sQs[d4] + k4.y * sQs[d4 + 1] + k4.z * sQs[d4 + 2] + k4.w * sQs[d4 + 3];
    }
    coarse[h * TOK + n] = cacc * SCALE;

    // main: 64-col f32x2 accumulation
    unsigned long long acc2[32];
#pragma unroll
    for (int i = 0; i < 32; i++) acc2[i] = 0ull;

    const uint32_t qrow = sQb + tid * (OQ_PAD * 4);
#pragma unroll 8
    for (int d1 = 0; d1 < 64; d1++) {
        unsigned long long qd = dup2(__uint_as_float(lds32(qrow + d1 * 4)));
        const uint32_t mrow = sMb + d1 * 256;
#pragma unroll
        for (int c = 0; c < 16; c++) {
            unsigned long long m0, m1;
            lds_v2u64(mrow + c * 16, m0, m1);
            acc2[c * 2]     = fma2(qd, m0, acc2[c * 2]);
            acc2[c * 2 + 1] = fma2(qd, m1, acc2[c * 2 + 1]);
        }
    }

    float* op = &out[((size_t)h * TOK + n) * DH];
#pragma unroll
    for (int c = 0; c < 16; c++) {
        float4 v;
        unpack2(acc2[c * 2], v.x, v.y);
        unpack2(acc2[c * 2 + 1], v.z, v.w);
        v.x *= SCALE; v.y *= SCALE; v.z *= SCALE; v.w *= SCALE;
        *reinterpret_cast<float4*>(&op[c * 4]) = v;
    }
}

// ---------------------------------------------------------------------------
extern "C" void kernel_launch(void* const* d_in, const int* in_sizes, int n_in,
                              void* d_out, int out_size) {
    const float* x = (const float*)d_in[0];   // [512, 4096]
    const float* W = (const float*)d_in[1];   // [512, 1536]
    const float* b = (const float*)d_in[2];   // [1536]

    float* coarse = (float*)d_out;
    float* out    = (float*)d_out + HEADS * TOK;

    __half *ahi, *bhi;
    cudaGetSymbolAddress((void**)&ahi, g_a_hi);
    cudaGetSymbolAddress((void**)&bhi, g_b_hi);

    cudaFuncSetAttribute(qkv_gemm_mma, cudaFuncAttributeMaxDynamicSharedMemorySize, SM_TOT);
    cudaFuncSetAttribute(out_kernel, cudaFuncAttributeMaxDynamicSharedMemorySize, OSM_TOT);

    conv_transpose<<<dim3(TOK / 32, EMB / 32), 256>>>(x, ahi, TOK);
    conv_transpose<<<dim3(QKVN / 32, EMB / 32), 256>>>(W, bhi, QKVN);

    qkv_gemm_mma<<<dim3(QKVN / GBN, TOK / GBM), 256, SM_TOT>>>(b);

    ktv_kernel<<<dim3(HEADS, 32), 128>>>();
    ktv_reduce<<<128, 256>>>();
    out_kernel<<<dim3(HEADS, 32), 128, OSM_TOT>>>(coarse, out);
}